// round 13
// baseline (speedup 1.0000x reference)
#include <cuda_runtime.h>
#include <cuda_fp16.h>
#include <cstdint>
#include <cstdio>

// ---------------- problem dims (fixed) ----------------
#define NTOK   18000      // F*H*W = 12*30*50
#define MPAD   18048      // padded to multiple of 128
#define DIMC   1536
#define NHEAD  12
#define HDIM   128
#define NBLK   150        // FB*HB*WB = 3*5*10
#define PBLK   120        // P1*P2*P3 = 4*6*5
#define EPSF   1e-6f

typedef unsigned long long ull;

// ---------------- mma / ldmatrix helpers ----------------
__device__ __forceinline__ uint32_t smem_u32(const void* p) {
    uint32_t a;
    asm("{ .reg .u64 t; cvta.to.shared.u64 t, %1; cvt.u32.u64 %0, t; }" : "=r"(a) : "l"(p));
    return a;
}
__device__ __forceinline__ void cp_async16(uint32_t dst, const void* src) {
    asm volatile("cp.async.cg.shared.global [%0], [%1], 16;" :: "r"(dst), "l"(src) : "memory");
}
__device__ __forceinline__ void ldm_x4(uint32_t* r, uint32_t addr) {
    asm volatile("ldmatrix.sync.aligned.m8n8.x4.shared.b16 {%0,%1,%2,%3}, [%4];"
                 : "=r"(r[0]), "=r"(r[1]), "=r"(r[2]), "=r"(r[3]) : "r"(addr));
}
__device__ __forceinline__ void ldm_x4_t(uint32_t* r, uint32_t addr) {
    asm volatile("ldmatrix.sync.aligned.m8n8.x4.trans.shared.b16 {%0,%1,%2,%3}, [%4];"
                 : "=r"(r[0]), "=r"(r[1]), "=r"(r[2]), "=r"(r[3]) : "r"(addr));
}
__device__ __forceinline__ void mma16816(float* c, const uint32_t* a, const uint32_t* b) {
    asm volatile("mma.sync.aligned.m16n8k16.row.col.f32.f16.f16.f32 "
                 "{%0,%1,%2,%3}, {%4,%5,%6,%7}, {%8,%9}, {%0,%1,%2,%3};"
                 : "+f"(c[0]), "+f"(c[1]), "+f"(c[2]), "+f"(c[3])
                 : "r"(a[0]), "r"(a[1]), "r"(a[2]), "r"(a[3]), "r"(b[0]), "r"(b[1]));
}
__device__ __forceinline__ uint32_t h2pack(float a, float b) {
    __half2 h = __floats2half2_rn(a, b);
    return *(uint32_t*)&h;
}
__device__ __forceinline__ uint32_t h2packlo(float a, float b, uint32_t hp) {
    __half2 h = *(__half2*)&hp;
    float2 hf = __half22float2(h);
    __half2 l = __floats2half2_rn(a - hf.x, b - hf.y);
    return *(uint32_t*)&l;
}

// ---------------- scratch ----------------
__device__ float Qbuf[NTOK * DIMC];      // pre-rope normed q (fp32, for qk)
__device__ float Kbuf[NTOK * DIMC];      // pre-rope normed k (fp32, for qk)
__device__ float QKbuf[NHEAD * NBLK * PBLK];
__device__ float WBLKbuf[NBLK * NBLK];

// fp16 operand buffers
__device__ __half Xh[MPAD * DIMC];
__device__ __half AOh[MPAD * DIMC];      // zero-init; pad rows never written
__device__ __half Wh4[4][DIMC * DIMC];
__device__ __half Vh[NTOK * DIMC];
__device__ __half Vl[NTOK * DIMC];
__device__ __half QRh[NTOK * DIMC];
__device__ __half QRl[NTOK * DIMC];
__device__ __half KRh[NTOK * DIMC];
__device__ __half KRl[NTOK * DIMC];
__device__ __half KVah[NHEAD * NBLK * HDIM * HDIM];
__device__ __half KVal[NHEAD * NBLK * HDIM * HDIM];
__device__ __half KVMh[NHEAD * NBLK * HDIM * HDIM];
__device__ __half KVMl[NHEAD * NBLK * HDIM * HDIM];
__device__ __half WBh[160 * 160];
__device__ __half WBl[160 * 160];

__device__ __forceinline__ int tok_of(int nb, int p) {
    int fb = nb / 50, hb = (nb / 10) % 5, wb = nb % 10;
    int p1 = p / 30, p2 = (p / 5) % 6, p3 = p % 5;
    int f = fb * 4 + p1, h = hb * 6 + p2, w = wb * 5 + p3;
    return (f * 30 + h) * 50 + w;
}

// ---------------- W_BLK ----------------
__global__ void wblk_kernel() {
    int j = blockIdx.x;
    int i = threadIdx.x;
    __shared__ double ssum[256];
    double m = 0.0;
    if (i < NBLK) {
        int fi = i / 50, hi = (i / 10) % 5, wi = i % 10;
        int fj = j / 50, hj = (j / 10) % 5, wj = j % 10;
        double df = fi - fj, dh = hi - hj, dw = wi - wj;
        double d = sqrt(df * df + dh * dh + dw * dw);
        m = 1.0 - d / sqrt(101.0);
    }
    ssum[i] = m;
    __syncthreads();
    for (int s = 128; s > 0; s >>= 1) {
        if (i < s) ssum[i] += ssum[i + s];
        __syncthreads();
    }
    if (i < NBLK) {
        float w = (float)(m / ssum[0]);
        WBLKbuf[i * NBLK + j] = w;
        __half h = __float2half(w);
        WBh[i * 160 + j] = h;
        WBl[i * 160 + j] = __float2half(w - __half2float(h));
    }
}

// ---------------- fp32 -> fp16 ----------------
__global__ void conv_half(const float* __restrict__ src, __half* __restrict__ dst, int n, int ntot) {
    int i = blockIdx.x * 256 + threadIdx.x;
    if (i >= ntot) return;
    float v = (i < n) ? src[i] : 0.f;
    dst[i] = __float2half(v);
}

__global__ void conv_w4(const float* __restrict__ w0, const float* __restrict__ w1,
                        const float* __restrict__ w2, const float* __restrict__ w3) {
    int y = blockIdx.y;
    const float* src = (y == 0) ? w0 : (y == 1) ? w1 : (y == 2) ? w2 : w3;
    int i = blockIdx.x * 256 + threadIdx.x;
    Wh4[y][i] = __float2half(src[i]);
}

// ---------------- pipelined fp16 1-pass tensor-core GEMM ----------------
#define KC      32
#define NCHUNK  (DIMC / KC)              // 48
#define TILEB   (128 * 64)               // 8192 B per operand tile
#define STAGEB  (2 * TILEB)              // 16384 B (A, B)
#define NSTAGE  4
#define GEMM_SMEM (NSTAGE * STAGEB)      // 65536 B -> 2 CTAs/SM

__device__ __forceinline__ void gemm_core(
    const __half* __restrict__ A, const __half* __restrict__ B,
    const float* __restrict__ bias, float* __restrict__ C,
    __half* __restrict__ VhOut, __half* __restrict__ VlOut, int M,
    int m0, int n0, uint32_t sb)
{
    int tid = threadIdx.x;
    int wid = tid >> 5, lane = tid & 31;
    int wm = (wid & 1) * 64;
    int wn = (wid >> 1) * 32;
    int lr = lane >> 2, lc = lane & 3;
    int q = lane >> 3, rr = lane & 7;

    int a_row = (q & 1) * 8 + rr;
    int a_seg0 = q >> 1;
    int b_row = (q >> 1) * 8 + rr;
    int b_seg0 = q & 1;
    int swA = (a_row >> 1) & 3;
    int swB = (b_row >> 1) & 3;
    uint32_t rowbA = (uint32_t)(wm + a_row) * 64;
    uint32_t rowbB = (uint32_t)(wn + b_row) * 64;

    float acc[4][4][4];
#pragma unroll
    for (int i = 0; i < 4; i++)
#pragma unroll
        for (int j = 0; j < 4; j++)
#pragma unroll
            for (int r = 0; r < 4; r++) acc[i][j][r] = 0.f;

    const __half* gptr[4];
    uint32_t sof[4];
#pragma unroll
    for (int i = 0; i < 4; i++) {
        int idx = tid + i * 256;
        int t = idx >> 9, row = (idx >> 2) & 127, seg = idx & 3;
        const __half* g = (t == 0) ? (A + (size_t)(m0 + row) * DIMC + seg * 8)
                                   : (B + (size_t)(n0 + row) * DIMC + seg * 8);
        gptr[i] = g;
        sof[i] = (uint32_t)(t * TILEB + row * 64 + ((seg ^ ((row >> 1) & 3)) * 16));
    }

    auto load_chunk = [&](int c, int st) {
        uint32_t sd = sb + st * STAGEB;
        size_t kof = (size_t)c * KC;
#pragma unroll
        for (int i = 0; i < 4; i++)
            cp_async16(sd + sof[i], gptr[i] + kof);
        asm volatile("cp.async.commit_group;" ::: "memory");
    };

    load_chunk(0, 0);
    load_chunk(1, 1);
    load_chunk(2, 2);
    for (int c = 0; c < NCHUNK; c++) {
        if (c < NCHUNK - 2)
            asm volatile("cp.async.wait_group 2;" ::: "memory");
        else if (c == NCHUNK - 2)
            asm volatile("cp.async.wait_group 1;" ::: "memory");
        else
            asm volatile("cp.async.wait_group 0;" ::: "memory");
        __syncthreads();
        uint32_t tb = sb + (c & 3) * STAGEB;
        uint32_t bA = tb + rowbA;
        uint32_t bB = tb + TILEB + rowbB;

        {
            uint32_t offA = (uint32_t)((a_seg0 ^ swA) * 16);
            uint32_t offB = (uint32_t)((b_seg0 ^ swB) * 16);
            uint32_t ah[4][4], bh[2][4];
#pragma unroll
            for (int mt = 0; mt < 4; mt++)
                ldm_x4(ah[mt], bA + mt * 1024 + offA);
#pragma unroll
            for (int nt2 = 0; nt2 < 2; nt2++)
                ldm_x4(bh[nt2], bB + nt2 * 1024 + offB);
#pragma unroll
            for (int mt = 0; mt < 4; mt++)
#pragma unroll
                for (int nt = 0; nt < 4; nt++)
                    mma16816(acc[mt][nt], ah[mt], &bh[nt >> 1][(nt & 1) * 2]);
        }
        if (c + 3 < NCHUNK) load_chunk(c + 3, (c + 3) & 3);
        {
            uint32_t offA = (uint32_t)(((a_seg0 + 2) ^ swA) * 16);
            uint32_t offB = (uint32_t)(((b_seg0 + 2) ^ swB) * 16);
            uint32_t ah[4][4], bh[2][4];
#pragma unroll
            for (int mt = 0; mt < 4; mt++)
                ldm_x4(ah[mt], bA + mt * 1024 + offA);
#pragma unroll
            for (int nt2 = 0; nt2 < 2; nt2++)
                ldm_x4(bh[nt2], bB + nt2 * 1024 + offB);
#pragma unroll
            for (int mt = 0; mt < 4; mt++)
#pragma unroll
                for (int nt = 0; nt < 4; nt++)
                    mma16816(acc[mt][nt], ah[mt], &bh[nt >> 1][(nt & 1) * 2]);
        }
    }

#pragma unroll
    for (int mt = 0; mt < 4; mt++) {
        int m = m0 + wm + mt * 16 + lr;
#pragma unroll
        for (int nt = 0; nt < 4; nt++) {
            int col = n0 + wn + nt * 8 + lc * 2;
            float bx = bias[col], by = bias[col + 1];
            if (VhOut) {
                if (m < M) {
                    float v0 = acc[mt][nt][0] + bx, v1 = acc[mt][nt][1] + by;
                    uint32_t hp = h2pack(v0, v1);
                    *(uint32_t*)(VhOut + (size_t)m * DIMC + col) = hp;
                    *(uint32_t*)(VlOut + (size_t)m * DIMC + col) = h2packlo(v0, v1, hp);
                }
                if (m + 8 < M) {
                    float v0 = acc[mt][nt][2] + bx, v1 = acc[mt][nt][3] + by;
                    uint32_t hp = h2pack(v0, v1);
                    *(uint32_t*)(VhOut + (size_t)(m + 8) * DIMC + col) = hp;
                    *(uint32_t*)(VlOut + (size_t)(m + 8) * DIMC + col) = h2packlo(v0, v1, hp);
                }
            } else {
                if (m < M) {
                    float2 v = make_float2(acc[mt][nt][0] + bx, acc[mt][nt][1] + by);
                    *(float2*)(C + (size_t)m * DIMC + col) = v;
                }
                if (m + 8 < M) {
                    float2 v = make_float2(acc[mt][nt][2] + bx, acc[mt][nt][3] + by);
                    *(float2*)(C + (size_t)(m + 8) * DIMC + col) = v;
                }
            }
        }
    }
}

// Q and K projections (z in {0,1}) on the main stream
__global__ __launch_bounds__(256, 2) void gemm_qk(
    const float* __restrict__ bq, const float* __restrict__ bk)
{
    extern __shared__ __align__(16) char smem[];
    uint32_t sb = smem_u32(smem);
    int z = blockIdx.z;
    const float* bias = (z == 0) ? bq : bk;
    float* C = (z == 0) ? Qbuf : Kbuf;
    gemm_core(Xh, Wh4[z], bias, C, (__half*)0, (__half*)0, NTOK,
              blockIdx.y * 128, blockIdx.x * 128, sb);
}

// V projection on a forked stream
__global__ __launch_bounds__(256, 2) void gemm_v(const float* __restrict__ bv)
{
    extern __shared__ __align__(16) char smem[];
    uint32_t sb = smem_u32(smem);
    gemm_core(Xh, Wh4[2], bv, (float*)0, Vh, Vl, NTOK,
              blockIdx.y * 128, blockIdx.x * 128, sb);
}

__global__ __launch_bounds__(256, 2) void gemm_out(const float* __restrict__ bo, float* __restrict__ out)
{
    extern __shared__ __align__(16) char smem[];
    uint32_t sb = smem_u32(smem);
    gemm_core(AOh, Wh4[3], bo, out, (__half*)0, (__half*)0, NTOK,
              blockIdx.y * 128, blockIdx.x * 128, sb);
}

// ---------------- fused rmsnorm + relu + eps + RoPE ----------------
__global__ void rmsnorm_rope_kernel(const float* __restrict__ nqw, const float* __restrict__ nkw,
                                    const float* __restrict__ fc, const float* __restrict__ fs) {
    int n = blockIdx.x;
    bool isK = blockIdx.y;
    float* buf = isK ? Kbuf : Qbuf;
    __half* rh = isK ? KRh : QRh;
    __half* rl = isK ? KRl : QRl;
    const float* w = isK ? nkw : nqw;
    int tid = threadIdx.x;
    size_t base = (size_t)n * DIMC;
    float2* b2 = (float2*)(buf + base);
    const float2* w2 = (const float2*)w;

    int f = n / 1500, rem = n % 1500;
    int hh = rem / 50, ww = rem % 50;

    float2 v[3];
    float ss = 0.f;
#pragma unroll
    for (int t = 0; t < 3; t++) {
        v[t] = b2[tid + t * 256];
        ss += v[t].x * v[t].x + v[t].y * v[t].y;
    }
    for (int o = 16; o > 0; o >>= 1) ss += __shfl_xor_sync(0xffffffffu, ss, o);
    __shared__ float red[8];
    __shared__ float stot;
    if ((tid & 31) == 0) red[tid >> 5] = ss;
    __syncthreads();
    if (tid == 0) {
        float t = 0.f;
        for (int i = 0; i < 8; i++) t += red[i];
        stot = t;
    }
    __syncthreads();
    float sc = 1.0f / sqrtf(stot * (1.0f / DIMC) + EPSF);
#pragma unroll
    for (int t = 0; t < 3; t++) {
        int idx = tid + t * 256;
        float2 wv = w2[idx];
        float x0 = fmaxf(v[t].x * sc * wv.x, 0.f) + EPSF;
        float x1 = fmaxf(v[t].y * sc * wv.y, 0.f) + EPSF;
        b2[idx] = make_float2(x0, x1);
        int c = idx & 63;
        int pos = (c < 22) ? f : ((c < 43) ? hh : ww);
        float cs = fc[pos * 64 + c];
        float sn = fs[pos * 64 + c];
        float r0 = x0 * cs - x1 * sn;
        float r1 = x0 * sn + x1 * cs;
        uint32_t hp = h2pack(r0, r1);
        *(uint32_t*)(rh + base + 2 * idx) = hp;
        *(uint32_t*)(rl + base + 2 * idx) = h2packlo(r0, r1, hp);
    }
}

// ---------------- kv: tc fp16 3-pass + fused ksum/qk ----------------
#define T2ST  136                       // halves per smem row (272 B, 4-bank rotation)
#define T2B   (128 * T2ST * 2)          // 34816 B per tile
#define KV2_SMEM (4 * T2B + 512)        // + ks[128]

__global__ __launch_bounds__(256) void kv_kernel() {
    extern __shared__ __align__(16) char smem[];
    uint32_t sb = smem_u32(smem);
    float* ksArr = (float*)(smem + 4 * T2B);
    int b = blockIdx.x;
    int hh = b / NBLK, nb = b % NBLK;
    int tid = threadIdx.x;

    // zero k-pad rows 120..127 (first 256B of each row) in all 4 tiles
    for (int i = tid; i < 4 * 8 * 16; i += 256) {
        int t = i >> 7, r = (i >> 4) & 7, s = i & 15;
        *(uint4*)(smem + t * T2B + (120 + r) * (T2ST * 2) + s * 16) = make_uint4(0, 0, 0, 0);
    }
    // group A: rows 0..63 of all 4 tiles
#pragma unroll
    for (int i = 0; i < 16; i++) {
        int idx = tid + i * 256;
        int t = idx >> 10;
        int rem = idx & 1023;
        int row = rem >> 4, seg = rem & 15;
        int tok = tok_of(nb, row);
        const __half* g = (t == 0) ? KRh : (t == 1) ? KRl : (t == 2) ? Vh : Vl;
        g += (size_t)tok * DIMC + hh * HDIM + seg * 8;
        cp_async16(sb + t * T2B + row * (T2ST * 2) + seg * 16, g);
    }
    asm volatile("cp.async.commit_group;" ::: "memory");
    // group B: rows 64..119
#pragma unroll
    for (int i = 0; i < 14; i++) {
        int idx = tid + i * 256;
        int t = idx / 896;
        int rem = idx - t * 896;
        int row = 64 + (rem >> 4), seg = rem & 15;
        int tok = tok_of(nb, row);
        const __half* g = (t == 0) ? KRh : (t == 1) ? KRl : (t == 2) ? Vh : Vl;
        g += (size_t)tok * DIMC + hh * HDIM + seg * 8;
        cp_async16(sb + t * T2B + row * (T2ST * 2) + seg * 16, g);
    }
    asm volatile("cp.async.commit_group;" ::: "memory");

    // fused ksum + qk while cp.async groups are in flight
    if (tid < HDIM) {
        float a = 0.f;
        for (int p = 0; p < PBLK; p++)
            a += Kbuf[(size_t)tok_of(nb, p) * DIMC + hh * HDIM + tid];
        ksArr[tid] = a;
    }
    __syncthreads();
    if (tid < PBLK) {
        const float* qp = Qbuf + (size_t)tok_of(nb, tid) * DIMC + hh * HDIM;
        float s = 0.f;
#pragma unroll 4
        for (int d = 0; d < HDIM; d++) s += qp[d] * ksArr[d];
        QKbuf[b * PBLK + tid] = s;
    }

    int wid = tid >> 5, lane = tid & 31;
    int q = lane >> 3, rr = lane & 7;
    int wm = (wid & 3) * 32, wn = (wid >> 2) * 64;   // d, e
    uint32_t bKRh = sb, bKRl = sb + T2B, bVh = sb + 2 * T2B, bVl = sb + 3 * T2B;

    float acc[2][8][4];
#pragma unroll
    for (int i = 0; i < 2; i++)
#pragma unroll
        for (int j = 0; j < 8; j++)
#pragma unroll
            for (int r = 0; r < 4; r++) acc[i][j][r] = 0.f;

    asm volatile("cp.async.wait_group 1;" ::: "memory");
    __syncthreads();

#pragma unroll
    for (int ks = 0; ks < 8; ks++) {
        if (ks == 4) {
            asm volatile("cp.async.wait_group 0;" ::: "memory");
            __syncthreads();
        }
        int p0 = ks * 16;
        uint32_t ah[2][4], al[2][4], bh[4][4], bl[4][4];
#pragma unroll
        for (int mt = 0; mt < 2; mt++) {
            int d0 = wm + mt * 16;
            uint32_t ad = (uint32_t)((p0 + (q >> 1) * 8 + rr) * T2ST + d0 + (q & 1) * 8) * 2;
            ldm_x4_t(ah[mt], bKRh + ad);
            ldm_x4_t(al[mt], bKRl + ad);
        }
#pragma unroll
        for (int nt2 = 0; nt2 < 4; nt2++) {
            int e0 = wn + nt2 * 16;
            uint32_t bd = (uint32_t)((p0 + (q & 1) * 8 + rr) * T2ST + e0 + (q >> 1) * 8) * 2;
            ldm_x4_t(bh[nt2], bVh + bd);
            ldm_x4_t(bl[nt2], bVl + bd);
        }
#pragma unroll
        for (int mt = 0; mt < 2; mt++)
#pragma unroll
            for (int nt = 0; nt < 8; nt++) {
                const uint32_t* pbh = &bh[nt >> 1][(nt & 1) * 2];
                const uint32_t* pbl = &bl[nt >> 1][(nt & 1) * 2];
                mma16816(acc[mt][nt], ah[mt], pbh);
                mma16816(acc[mt][nt], ah[mt], pbl);
                mma16816(acc[mt][nt], al[mt], pbh);
            }
    }

    int lr = lane >> 2, lc = lane & 3;
    size_t db = (size_t)b * HDIM * HDIM;
#pragma unroll
    for (int mt = 0; mt < 2; mt++) {
        int d = wm + mt * 16 + lr;
#pragma unroll
        for (int nt = 0; nt < 8; nt++) {
            int e = wn + nt * 8 + lc * 2;
            {
                float v0 = acc[mt][nt][0], v1 = acc[mt][nt][1];
                uint32_t hp = h2pack(v0, v1);
                *(uint32_t*)(KVah + db + d * HDIM + e) = hp;
                *(uint32_t*)(KVal + db + d * HDIM + e) = h2packlo(v0, v1, hp);
            }
            {
                float v0 = acc[mt][nt][2], v1 = acc[mt][nt][3];
                uint32_t hp = h2pack(v0, v1);
                *(uint32_t*)(KVah + db + (d + 8) * HDIM + e) = hp;
                *(uint32_t*)(KVal + db + (d + 8) * HDIM + e) = h2packlo(v0, v1, hp);
            }
        }
    }
}

// ---------------- mix on tensor cores ----------------
#define MXST  168
#define MWB   (160 * MXST * 2)
#define MKST  136
#define MKB   (160 * MKST * 2)
#define MIX2_SMEM (2 * MWB + 2 * MKB)

__global__ __launch_bounds__(256) void mix_tc_kernel() {
    extern __shared__ __align__(16) char smem[];
    uint32_t sb = smem_u32(smem);
    int hh = blockIdx.y, xt = blockIdx.x;
    int tid = threadIdx.x;

    uint32_t bWh = sb, bWl = sb + MWB, bKh = sb + 2 * MWB, bKl = sb + 2 * MWB + MKB;

    for (int i = tid; i < 340; i += 256) {
        int t = i / 170, rem = i % 170;
        int r = rem / 17, s = rem % 17;
        *(uint4*)(smem + 2 * MWB + t * MKB + (150 + r) * (MKST * 2) + s * 16) = make_uint4(0, 0, 0, 0);
    }
#pragma unroll
    for (int i = 0; i < 25; i++) {
        int idx = tid + i * 256;
        int t = idx / 3200, rem = idx % 3200;
        int row = rem / 20, seg = rem % 20;
        const __half* g = ((t == 0) ? WBh : WBl) + row * 160 + seg * 8;
        cp_async16(sb + t * MWB + row * (MXST * 2) + seg * 16, g);
    }
#pragma unroll
    for (int i = 0; i < 19; i++) {
        int idx = tid + i * 256;
        if (idx < 4800) {
            int t = idx / 2400, rem = idx % 2400;
            int row = rem >> 4, seg = rem & 15;
            const __half* g = ((t == 0) ? KVah : KVal)
                            + ((size_t)(hh * NBLK + row)) * (HDIM * HDIM) + xt * 128 + seg * 8;
            cp_async16(sb + 2 * MWB + t * MKB + row * (MKST * 2) + seg * 16, g);
        }
    }
    asm volatile("cp.async.commit_group;" ::: "memory");
    asm volatile("cp.async.wait_group 0;" ::: "memory");
    __syncthreads();

    int wid = tid >> 5, lane = tid & 31;
    int q = lane >> 3, rr = lane & 7;
    int wm = (wid & 1) * 80;
    int wn = (wid >> 1) * 32;

    float acc[5][4][4];
#pragma unroll
    for (int i = 0; i < 5; i++)
#pragma unroll
        for (int j = 0; j < 4; j++)
#pragma unroll
            for (int r = 0; r < 4; r++) acc[i][j][r] = 0.f;

#pragma unroll
    for (int ks = 0; ks < 10; ks++) {
        int k0 = ks * 16;
        uint32_t ah[5][4], al[5][4], bh[2][4], bl[2][4];
#pragma unroll
        for (int mt = 0; mt < 5; mt++) {
            int m0 = wm + mt * 16;
            uint32_t ad = (uint32_t)((m0 + (q & 1) * 8 + rr) * MXST + k0 + (q >> 1) * 8) * 2;
            ldm_x4(ah[mt], bWh + ad);
            ldm_x4(al[mt], bWl + ad);
        }
#pragma unroll
        for (int nt2 = 0; nt2 < 2; nt2++) {
            int e0 = wn + nt2 * 16;
            uint32_t bd = (uint32_t)((k0 + (q & 1) * 8 + rr) * MKST + e0 + (q >> 1) * 8) * 2;
            ldm_x4_t(bh[nt2], bKh + bd);
            ldm_x4_t(bl[nt2], bKl + bd);
        }
#pragma unroll
        for (int mt = 0; mt < 5; mt++)
#pragma unroll
            for (int nt = 0; nt < 4; nt++) {
                const uint32_t* pbh = &bh[nt >> 1][(nt & 1) * 2];
                const uint32_t* pbl = &bl[nt >> 1][(nt & 1) * 2];
                mma16816(acc[mt][nt], ah[mt], pbh);
                mma16816(acc[mt][nt], ah[mt], pbl);
                mma16816(acc[mt][nt], al[mt], pbh);
            }
    }

    int lr = lane >> 2, lc = lane & 3;
#pragma unroll
    for (int mt = 0; mt < 5; mt++) {
        int o = wm + mt * 16 + lr;
#pragma unroll
        for (int half = 0; half < 2; half++) {
            int oo = o + half * 8;
            if (oo < NBLK) {
                size_t gb = ((size_t)(hh * NBLK + oo)) * (HDIM * HDIM) + xt * 128 + wn;
#pragma unroll
                for (int nt = 0; nt < 4; nt++) {
                    int e = nt * 8 + lc * 2;
                    float v0 = acc[mt][nt][2 * half];
                    float v1 = acc[mt][nt][2 * half + 1];
                    uint32_t hp = h2pack(v0, v1);
                    *(uint32_t*)(KVMh + gb + e) = hp;
                    *(uint32_t*)(KVMl + gb + e) = h2packlo(v0, v1, hp);
                }
            }
        }
    }
}

// ---------------- out: tc fp16 3-pass + fused norm; /norm -> AOh ----------------
#define OUT2_SMEM (4 * T2B + 512)

__global__ __launch_bounds__(256) void out_kernel() {
    extern __shared__ __align__(16) char smem[];
    uint32_t sb = smem_u32(smem);
    float* sNorm = (float*)(smem + 4 * T2B);
    int b = blockIdx.x;
    int hh = b / NBLK, nb = b % NBLK;
    int tid = threadIdx.x;

    // group A: QR both tiles (3840) + KVM rows 0..63 (2048) = 5888 segs -> 23/thread
#pragma unroll
    for (int i = 0; i < 23; i++) {
        int idx = tid + i * 256;
        if (idx < 3840) {
            int t = idx / 1920;
            int rem = idx - t * 1920;
            int row = rem >> 4, seg = rem & 15;
            int tok = tok_of(nb, row);
            const __half* g = (t == 0) ? QRh : QRl;
            g += (size_t)tok * DIMC + hh * HDIM + seg * 8;
            cp_async16(sb + t * T2B + row * (T2ST * 2) + seg * 16, g);
        } else if (idx < 5888) {
            int idx2 = idx - 3840;
            int t = idx2 >> 10;
            int rem = idx2 & 1023;
            int row = rem >> 4, seg = rem & 15;
            const __half* g = (t == 0) ? KVMh : KVMl;
            g += (size_t)b * HDIM * HDIM + row * HDIM + seg * 8;
            cp_async16(sb + (2 + t) * T2B + row * (T2ST * 2) + seg * 16, g);
        }
    }
    asm volatile("cp.async.commit_group;" ::: "memory");
    // group B: KVM rows 64..127
#pragma unroll
    for (int i = 0; i < 8; i++) {
        int idx = tid + i * 256;
        int t = idx >> 10;
        int rem = idx & 1023;
        int row = 64 + (rem >> 4), seg = rem & 15;
        const __half* g = (t == 0) ? KVMh : KVMl;
        g += (size_t)b * HDIM * HDIM + row * HDIM + seg * 8;
        cp_async16(sb + (2 + t) * T2B + row * (T2ST * 2) + seg * 16, g);
    }
    asm volatile("cp.async.commit_group;" ::: "memory");

    // fused norm: overlap with in-flight cp.async loads
    if (tid < PBLK) {
        float a = EPSF;
        const float* wrow = WBLKbuf + nb * NBLK;
        const float* qkcol = QKbuf + (size_t)hh * NBLK * PBLK + tid;
        for (int i = 0; i < NBLK; i++)
            a += wrow[i] * qkcol[(size_t)i * PBLK];
        sNorm[tid] = a;
    }

    int wid = tid >> 5, lane = tid & 31;
    int q = lane >> 3, rr = lane & 7;
    int wm = (wid & 1) * 64, wn = (wid >> 1) * 32;   // p, e
    uint32_t bQh = sb, bQl = sb + T2B, bMh = sb + 2 * T2B, bMl = sb + 3 * T2B;

    float acc[4][4][4];
#pragma unroll
    for (int i = 0; i < 4; i++)
#pragma unroll
        for (int j = 0; j < 4; j++)
#pragma unroll
            for (int r = 0; r < 4; r++) acc[i][j][r] = 0.f;

    asm volatile("cp.async.wait_group 1;" ::: "memory");
    __syncthreads();

#pragma unroll
    for (int ks = 0; ks < 8; ks++) {
        if (ks == 4) {
            asm volatile("cp.async.wait_group 0;" ::: "memory");
            __syncthreads();
        }
        int d0 = ks * 16;
        uint32_t ah[4][4], al[4][4], bh[2][4], bl[2][4];
#pragma unroll
        for (int mt = 0; mt < 4; mt++) {
            int m0 = wm + mt * 16;
            uint32_t ad = (uint32_t)((m0 + (q & 1) * 8 + rr) * T2ST + d0 + (q >> 1) * 8) * 2;
            ldm_x4(ah[mt], bQh + ad);
            ldm_x4(al[mt], bQl + ad);
        }
#pragma unroll
        for (int nt2 = 0; nt2 < 2; nt2++) {
            int e0 = wn + nt2 * 16;
            uint32_t bd = (uint32_t)((d0 + (q & 1) * 8 + rr) * T2ST + e0 + (q >> 1) * 8) * 2;
            ldm_x4_t(bh[nt2], bMh + bd);
            ldm_x4_t(bl[nt2], bMl + bd);
        }
#pragma unroll
        for (int mt = 0; mt < 4; mt++)
#pragma unroll
            for (int nt = 0; nt < 4; nt++) {
                const uint32_t* pbh = &bh[nt >> 1][(nt & 1) * 2];
                const uint32_t* pbl = &bl[nt >> 1][(nt & 1) * 2];
                mma16816(acc[mt][nt], ah[mt], pbh);
                mma16816(acc[mt][nt], ah[mt], pbl);
                mma16816(acc[mt][nt], al[mt], pbh);
            }
    }

    int lr = lane >> 2, lc = lane & 3;
#pragma unroll
    for (int mt = 0; mt < 4; mt++) {
        int p = wm + mt * 16 + lr;
#pragma unroll
        for (int half = 0; half < 2; half++) {
            int pp = p + half * 8;
            if (pp < PBLK) {
                float inv = 1.0f / sNorm[pp];
                int tok = tok_of(nb, pp);
                size_t gb = (size_t)tok * DIMC + hh * HDIM;
#pragma unroll
                for (int nt = 0; nt < 4; nt++) {
                    int e = wn + nt * 8 + lc * 2;
                    float v0 = acc[mt][nt][2 * half]     * inv;
                    float v1 = acc[mt][nt][2 * half + 1] * inv;
                    *(uint32_t*)(AOh + gb + e) = h2pack(v0, v1);
                }
            }
        }
    }
}

// ---------------- launch ----------------
extern "C" void kernel_launch(void* const* d_in, const int* in_sizes, int n_in,
                              void* d_out, int out_size) {
    const float* x   = (const float*)d_in[0];
    const float* fc  = (const float*)d_in[3];
    const float* fs  = (const float*)d_in[4];
    const float* wq  = (const float*)d_in[5];
    const float* bq  = (const float*)d_in[6];
    const float* wk  = (const float*)d_in[7];
    const float* bk  = (const float*)d_in[8];
    const float* wv  = (const float*)d_in[9];
    const float* bv  = (const float*)d_in[10];
    const float* wo  = (const float*)d_in[11];
    const float* bo  = (const float*)d_in[12];
    const float* nqw = (const float*)d_in[13];
    const float* nkw = (const float*)d_in[14];
    float* out = (float*)d_out;

    void* pxh;
    cudaGetSymbolAddress(&pxh, Xh);

    cudaFuncSetAttribute(gemm_qk,   cudaFuncAttributeMaxDynamicSharedMemorySize, GEMM_SMEM);
    cudaFuncSetAttribute(gemm_v,    cudaFuncAttributeMaxDynamicSharedMemorySize, GEMM_SMEM);
    cudaFuncSetAttribute(gemm_out,  cudaFuncAttributeMaxDynamicSharedMemorySize, GEMM_SMEM);
    cudaFuncSetAttribute(kv_kernel, cudaFuncAttributeMaxDynamicSharedMemorySize, KV2_SMEM);
    cudaFuncSetAttribute(mix_tc_kernel, cudaFuncAttributeMaxDynamicSharedMemorySize, MIX2_SMEM);
    cudaFuncSetAttribute(out_kernel, cudaFuncAttributeMaxDynamicSharedMemorySize, OUT2_SMEM);

    // side stream + events (created per call; kernel_launch runs only a few times)
    cudaStream_t s1;
    cudaStreamCreate(&s1);
    cudaEvent_t e1, e2;
    cudaEventCreateWithFlags(&e1, cudaEventDisableTiming);
    cudaEventCreateWithFlags(&e2, cudaEventDisableTiming);

    wblk_kernel<<<NBLK, 256>>>();
    conv_half<<<(MPAD * DIMC) / 256, 256>>>(x, (__half*)pxh, NTOK * DIMC, MPAD * DIMC);
    conv_w4<<<dim3((DIMC * DIMC) / 256, 4), 256>>>(wq, wk, wv, wo);

    // fork: V projection on s1 (independent of rmsnorm/qk path)
    cudaEventRecord(e1, 0);
    cudaStreamWaitEvent(s1, e1, 0);
    dim3 gv(DIMC / 128, MPAD / 128);
    gemm_v<<<gv, 256, GEMM_SMEM, s1>>>(bv);
    cudaEventRecord(e2, s1);

    // main path: Q/K projections -> rmsnorm/rope
    dim3 gqk(DIMC / 128, MPAD / 128, 2);
    gemm_qk<<<gqk, 256, GEMM_SMEM>>>(bq, bk);
    rmsnorm_rope_kernel<<<dim3(NTOK, 2), 256>>>(nqw, nkw, fc, fs);

    // join: kv needs V (s1) and KR (main)
    cudaStreamWaitEvent(0, e2, 0);
    kv_kernel<<<NHEAD * NBLK, 256, KV2_SMEM>>>();
    mix_tc_kernel<<<dim3(128, NHEAD), 256, MIX2_SMEM>>>();
    out_kernel<<<NHEAD * NBLK, 256, OUT2_SMEM>>>();

    dim3 go(DIMC / 128, MPAD / 128);
    gemm_out<<<go, 256, GEMM_SMEM>>>(bo, out);
}

// round 14
// speedup vs baseline: 1.4192x; 1.4192x over previous
#include <cuda_runtime.h>
#include <cuda_fp16.h>
#include <cstdint>
#include <cstdio>

// ---------------- problem dims (fixed) ----------------
#define NTOK   18000      // F*H*W = 12*30*50
#define MPAD   18048      // padded to multiple of 128
#define DIMC   1536
#define NHEAD  12
#define HDIM   128
#define NBLK   150        // FB*HB*WB = 3*5*10
#define PBLK   120        // P1*P2*P3 = 4*6*5
#define EPSF   1e-6f

typedef unsigned long long ull;

// ---------------- mma / ldmatrix helpers ----------------
__device__ __forceinline__ uint32_t smem_u32(const void* p) {
    uint32_t a;
    asm("{ .reg .u64 t; cvta.to.shared.u64 t, %1; cvt.u32.u64 %0, t; }" : "=r"(a) : "l"(p));
    return a;
}
__device__ __forceinline__ void cp_async16(uint32_t dst, const void* src) {
    asm volatile("cp.async.cg.shared.global [%0], [%1], 16;" :: "r"(dst), "l"(src) : "memory");
}
__device__ __forceinline__ void ldm_x4(uint32_t* r, uint32_t addr) {
    asm volatile("ldmatrix.sync.aligned.m8n8.x4.shared.b16 {%0,%1,%2,%3}, [%4];"
                 : "=r"(r[0]), "=r"(r[1]), "=r"(r[2]), "=r"(r[3]) : "r"(addr));
}
__device__ __forceinline__ void ldm_x4_t(uint32_t* r, uint32_t addr) {
    asm volatile("ldmatrix.sync.aligned.m8n8.x4.trans.shared.b16 {%0,%1,%2,%3}, [%4];"
                 : "=r"(r[0]), "=r"(r[1]), "=r"(r[2]), "=r"(r[3]) : "r"(addr));
}
__device__ __forceinline__ void mma16816(float* c, const uint32_t* a, const uint32_t* b) {
    asm volatile("mma.sync.aligned.m16n8k16.row.col.f32.f16.f16.f32 "
                 "{%0,%1,%2,%3}, {%4,%5,%6,%7}, {%8,%9}, {%0,%1,%2,%3};"
                 : "+f"(c[0]), "+f"(c[1]), "+f"(c[2]), "+f"(c[3])
                 : "r"(a[0]), "r"(a[1]), "r"(a[2]), "r"(a[3]), "r"(b[0]), "r"(b[1]));
}
__device__ __forceinline__ uint32_t h2pack(float a, float b) {
    __half2 h = __floats2half2_rn(a, b);
    return *(uint32_t*)&h;
}
__device__ __forceinline__ uint32_t h2packlo(float a, float b, uint32_t hp) {
    __half2 h = *(__half2*)&hp;
    float2 hf = __half22float2(h);
    __half2 l = __floats2half2_rn(a - hf.x, b - hf.y);
    return *(uint32_t*)&l;
}

// ---------------- scratch ----------------
__device__ float Qbuf[NTOK * DIMC];      // pre-rope normed q (fp32, for qk)
__device__ float Kbuf[NTOK * DIMC];      // pre-rope normed k (fp32, for qk)
__device__ float QKbuf[NHEAD * NBLK * PBLK];
__device__ float WBLKbuf[NBLK * NBLK];

// fp16 operand buffers
__device__ __half Xh[MPAD * DIMC];
__device__ __half AOh[MPAD * DIMC];      // zero-init; pad rows never written
__device__ __half Wh4[4][DIMC * DIMC];
__device__ __half Vh[NTOK * DIMC];
__device__ __half Vl[NTOK * DIMC];
__device__ __half QRh[NTOK * DIMC];
__device__ __half QRl[NTOK * DIMC];
__device__ __half KRh[NTOK * DIMC];
__device__ __half KRl[NTOK * DIMC];
__device__ __half KVah[NHEAD * NBLK * HDIM * HDIM];
__device__ __half KVal[NHEAD * NBLK * HDIM * HDIM];
__device__ __half KVMh[NHEAD * NBLK * HDIM * HDIM];
__device__ __half KVMl[NHEAD * NBLK * HDIM * HDIM];
__device__ __half WBh[160 * 160];
__device__ __half WBl[160 * 160];

__device__ __forceinline__ int tok_of(int nb, int p) {
    int fb = nb / 50, hb = (nb / 10) % 5, wb = nb % 10;
    int p1 = p / 30, p2 = (p / 5) % 6, p3 = p % 5;
    int f = fb * 4 + p1, h = hb * 6 + p2, w = wb * 5 + p3;
    return (f * 30 + h) * 50 + w;
}

// ---------------- W_BLK ----------------
__global__ void wblk_kernel() {
    int j = blockIdx.x;
    int i = threadIdx.x;
    __shared__ double ssum[256];
    double m = 0.0;
    if (i < NBLK) {
        int fi = i / 50, hi = (i / 10) % 5, wi = i % 10;
        int fj = j / 50, hj = (j / 10) % 5, wj = j % 10;
        double df = fi - fj, dh = hi - hj, dw = wi - wj;
        double d = sqrt(df * df + dh * dh + dw * dw);
        m = 1.0 - d / sqrt(101.0);
    }
    ssum[i] = m;
    __syncthreads();
    for (int s = 128; s > 0; s >>= 1) {
        if (i < s) ssum[i] += ssum[i + s];
        __syncthreads();
    }
    if (i < NBLK) {
        float w = (float)(m / ssum[0]);
        WBLKbuf[i * NBLK + j] = w;
        __half h = __float2half(w);
        WBh[i * 160 + j] = h;
        WBl[i * 160 + j] = __float2half(w - __half2float(h));
    }
}

// ---------------- fp32 -> fp16 ----------------
__global__ void conv_half(const float* __restrict__ src, __half* __restrict__ dst, int n, int ntot) {
    int i = blockIdx.x * 256 + threadIdx.x;
    if (i >= ntot) return;
    float v = (i < n) ? src[i] : 0.f;
    dst[i] = __float2half(v);
}

__global__ void conv_w4(const float* __restrict__ w0, const float* __restrict__ w1,
                        const float* __restrict__ w2, const float* __restrict__ w3) {
    int y = blockIdx.y;
    const float* src = (y == 0) ? w0 : (y == 1) ? w1 : (y == 2) ? w2 : w3;
    int i = blockIdx.x * 256 + threadIdx.x;
    Wh4[y][i] = __float2half(src[i]);
}

// ---------------- pipelined fp16 1-pass tensor-core GEMM ----------------
#define KC      32
#define NCHUNK  (DIMC / KC)              // 48
#define TILEB   (128 * 64)               // 8192 B per operand tile
#define STAGEB  (2 * TILEB)              // 16384 B (A, B)
#define NSTAGE  4
#define GEMM_SMEM (NSTAGE * STAGEB)      // 65536 B -> 2 CTAs/SM

__device__ __forceinline__ void gemm_core(
    const __half* __restrict__ A, const __half* __restrict__ B,
    const float* __restrict__ bias, float* __restrict__ C,
    __half* __restrict__ VhOut, __half* __restrict__ VlOut, int M,
    int m0, int n0, uint32_t sb)
{
    int tid = threadIdx.x;
    int wid = tid >> 5, lane = tid & 31;
    int wm = (wid & 1) * 64;
    int wn = (wid >> 1) * 32;
    int lr = lane >> 2, lc = lane & 3;
    int q = lane >> 3, rr = lane & 7;

    int a_row = (q & 1) * 8 + rr;
    int a_seg0 = q >> 1;
    int b_row = (q >> 1) * 8 + rr;
    int b_seg0 = q & 1;
    int swA = (a_row >> 1) & 3;
    int swB = (b_row >> 1) & 3;
    uint32_t rowbA = (uint32_t)(wm + a_row) * 64;
    uint32_t rowbB = (uint32_t)(wn + b_row) * 64;

    float acc[4][4][4];
#pragma unroll
    for (int i = 0; i < 4; i++)
#pragma unroll
        for (int j = 0; j < 4; j++)
#pragma unroll
            for (int r = 0; r < 4; r++) acc[i][j][r] = 0.f;

    const __half* gptr[4];
    uint32_t sof[4];
#pragma unroll
    for (int i = 0; i < 4; i++) {
        int idx = tid + i * 256;
        int t = idx >> 9, row = (idx >> 2) & 127, seg = idx & 3;
        const __half* g = (t == 0) ? (A + (size_t)(m0 + row) * DIMC + seg * 8)
                                   : (B + (size_t)(n0 + row) * DIMC + seg * 8);
        gptr[i] = g;
        sof[i] = (uint32_t)(t * TILEB + row * 64 + ((seg ^ ((row >> 1) & 3)) * 16));
    }

    auto load_chunk = [&](int c, int st) {
        uint32_t sd = sb + st * STAGEB;
        size_t kof = (size_t)c * KC;
#pragma unroll
        for (int i = 0; i < 4; i++)
            cp_async16(sd + sof[i], gptr[i] + kof);
        asm volatile("cp.async.commit_group;" ::: "memory");
    };

    load_chunk(0, 0);
    load_chunk(1, 1);
    load_chunk(2, 2);
    for (int c = 0; c < NCHUNK; c++) {
        if (c < NCHUNK - 2)
            asm volatile("cp.async.wait_group 2;" ::: "memory");
        else if (c == NCHUNK - 2)
            asm volatile("cp.async.wait_group 1;" ::: "memory");
        else
            asm volatile("cp.async.wait_group 0;" ::: "memory");
        __syncthreads();
        uint32_t tb = sb + (c & 3) * STAGEB;
        uint32_t bA = tb + rowbA;
        uint32_t bB = tb + TILEB + rowbB;

        {
            uint32_t offA = (uint32_t)((a_seg0 ^ swA) * 16);
            uint32_t offB = (uint32_t)((b_seg0 ^ swB) * 16);
            uint32_t ah[4][4], bh[2][4];
#pragma unroll
            for (int mt = 0; mt < 4; mt++)
                ldm_x4(ah[mt], bA + mt * 1024 + offA);
#pragma unroll
            for (int nt2 = 0; nt2 < 2; nt2++)
                ldm_x4(bh[nt2], bB + nt2 * 1024 + offB);
#pragma unroll
            for (int mt = 0; mt < 4; mt++)
#pragma unroll
                for (int nt = 0; nt < 4; nt++)
                    mma16816(acc[mt][nt], ah[mt], &bh[nt >> 1][(nt & 1) * 2]);
        }
        if (c + 3 < NCHUNK) load_chunk(c + 3, (c + 3) & 3);
        {
            uint32_t offA = (uint32_t)(((a_seg0 + 2) ^ swA) * 16);
            uint32_t offB = (uint32_t)(((b_seg0 + 2) ^ swB) * 16);
            uint32_t ah[4][4], bh[2][4];
#pragma unroll
            for (int mt = 0; mt < 4; mt++)
                ldm_x4(ah[mt], bA + mt * 1024 + offA);
#pragma unroll
            for (int nt2 = 0; nt2 < 2; nt2++)
                ldm_x4(bh[nt2], bB + nt2 * 1024 + offB);
#pragma unroll
            for (int mt = 0; mt < 4; mt++)
#pragma unroll
                for (int nt = 0; nt < 4; nt++)
                    mma16816(acc[mt][nt], ah[mt], &bh[nt >> 1][(nt & 1) * 2]);
        }
    }

#pragma unroll
    for (int mt = 0; mt < 4; mt++) {
        int m = m0 + wm + mt * 16 + lr;
#pragma unroll
        for (int nt = 0; nt < 4; nt++) {
            int col = n0 + wn + nt * 8 + lc * 2;
            float bx = bias[col], by = bias[col + 1];
            if (VhOut) {
                if (m < M) {
                    float v0 = acc[mt][nt][0] + bx, v1 = acc[mt][nt][1] + by;
                    uint32_t hp = h2pack(v0, v1);
                    *(uint32_t*)(VhOut + (size_t)m * DIMC + col) = hp;
                    *(uint32_t*)(VlOut + (size_t)m * DIMC + col) = h2packlo(v0, v1, hp);
                }
                if (m + 8 < M) {
                    float v0 = acc[mt][nt][2] + bx, v1 = acc[mt][nt][3] + by;
                    uint32_t hp = h2pack(v0, v1);
                    *(uint32_t*)(VhOut + (size_t)(m + 8) * DIMC + col) = hp;
                    *(uint32_t*)(VlOut + (size_t)(m + 8) * DIMC + col) = h2packlo(v0, v1, hp);
                }
            } else {
                if (m < M) {
                    float2 v = make_float2(acc[mt][nt][0] + bx, acc[mt][nt][1] + by);
                    *(float2*)(C + (size_t)m * DIMC + col) = v;
                }
                if (m + 8 < M) {
                    float2 v = make_float2(acc[mt][nt][2] + bx, acc[mt][nt][3] + by);
                    *(float2*)(C + (size_t)(m + 8) * DIMC + col) = v;
                }
            }
        }
    }
}

__global__ __launch_bounds__(256, 2) void gemm_qkv(
    const float* __restrict__ bq, const float* __restrict__ bk, const float* __restrict__ bv)
{
    extern __shared__ __align__(16) char smem[];
    uint32_t sb = smem_u32(smem);
    int z = blockIdx.z;
    if (z == 2) {
        gemm_core(Xh, Wh4[2], bv, (float*)0, Vh, Vl, NTOK,
                  blockIdx.y * 128, blockIdx.x * 128, sb);
    } else {
        const float* bias = (z == 0) ? bq : bk;
        float* C = (z == 0) ? Qbuf : Kbuf;
        gemm_core(Xh, Wh4[z], bias, C, (__half*)0, (__half*)0, NTOK,
                  blockIdx.y * 128, blockIdx.x * 128, sb);
    }
}

__global__ __launch_bounds__(256, 2) void gemm_out(const float* __restrict__ bo, float* __restrict__ out)
{
    extern __shared__ __align__(16) char smem[];
    uint32_t sb = smem_u32(smem);
    gemm_core(AOh, Wh4[3], bo, out, (__half*)0, (__half*)0, NTOK,
              blockIdx.y * 128, blockIdx.x * 128, sb);
}

// ---------------- fused rmsnorm + relu + eps + RoPE ----------------
__global__ void rmsnorm_rope_kernel(const float* __restrict__ nqw, const float* __restrict__ nkw,
                                    const float* __restrict__ fc, const float* __restrict__ fs) {
    int n = blockIdx.x;
    bool isK = blockIdx.y;
    float* buf = isK ? Kbuf : Qbuf;
    __half* rh = isK ? KRh : QRh;
    __half* rl = isK ? KRl : QRl;
    const float* w = isK ? nkw : nqw;
    int tid = threadIdx.x;
    size_t base = (size_t)n * DIMC;
    float2* b2 = (float2*)(buf + base);
    const float2* w2 = (const float2*)w;

    int f = n / 1500, rem = n % 1500;
    int hh = rem / 50, ww = rem % 50;

    float2 v[3];
    float ss = 0.f;
#pragma unroll
    for (int t = 0; t < 3; t++) {
        v[t] = b2[tid + t * 256];
        ss += v[t].x * v[t].x + v[t].y * v[t].y;
    }
    for (int o = 16; o > 0; o >>= 1) ss += __shfl_xor_sync(0xffffffffu, ss, o);
    __shared__ float red[8];
    __shared__ float stot;
    if ((tid & 31) == 0) red[tid >> 5] = ss;
    __syncthreads();
    if (tid == 0) {
        float t = 0.f;
        for (int i = 0; i < 8; i++) t += red[i];
        stot = t;
    }
    __syncthreads();
    float sc = 1.0f / sqrtf(stot * (1.0f / DIMC) + EPSF);
#pragma unroll
    for (int t = 0; t < 3; t++) {
        int idx = tid + t * 256;
        float2 wv = w2[idx];
        float x0 = fmaxf(v[t].x * sc * wv.x, 0.f) + EPSF;
        float x1 = fmaxf(v[t].y * sc * wv.y, 0.f) + EPSF;
        b2[idx] = make_float2(x0, x1);
        int c = idx & 63;
        int pos = (c < 22) ? f : ((c < 43) ? hh : ww);
        float cs = fc[pos * 64 + c];
        float sn = fs[pos * 64 + c];
        float r0 = x0 * cs - x1 * sn;
        float r1 = x0 * sn + x1 * cs;
        uint32_t hp = h2pack(r0, r1);
        *(uint32_t*)(rh + base + 2 * idx) = hp;
        *(uint32_t*)(rl + base + 2 * idx) = h2packlo(r0, r1, hp);
    }
}

// ---------------- kv: tc fp16 3-pass + fused ksum/qk ----------------
#define T2ST  136                       // halves per smem row (272 B, 4-bank rotation)
#define T2B   (128 * T2ST * 2)          // 34816 B per tile
#define KV2_SMEM (4 * T2B + 512)        // + ks[128]

__global__ __launch_bounds__(256) void kv_kernel() {
    extern __shared__ __align__(16) char smem[];
    uint32_t sb = smem_u32(smem);
    float* ksArr = (float*)(smem + 4 * T2B);
    int b = blockIdx.x;
    int hh = b / NBLK, nb = b % NBLK;
    int tid = threadIdx.x;

    // zero k-pad rows 120..127 in all 4 tiles
    for (int i = tid; i < 4 * 8 * 16; i += 256) {
        int t = i >> 7, r = (i >> 4) & 7, s = i & 15;
        *(uint4*)(smem + t * T2B + (120 + r) * (T2ST * 2) + s * 16) = make_uint4(0, 0, 0, 0);
    }
    // group A: rows 0..63 of all 4 tiles
#pragma unroll
    for (int i = 0; i < 16; i++) {
        int idx = tid + i * 256;
        int t = idx >> 10;
        int rem = idx & 1023;
        int row = rem >> 4, seg = rem & 15;
        int tok = tok_of(nb, row);
        const __half* g = (t == 0) ? KRh : (t == 1) ? KRl : (t == 2) ? Vh : Vl;
        g += (size_t)tok * DIMC + hh * HDIM + seg * 8;
        cp_async16(sb + t * T2B + row * (T2ST * 2) + seg * 16, g);
    }
    asm volatile("cp.async.commit_group;" ::: "memory");
    // group B: rows 64..119
#pragma unroll
    for (int i = 0; i < 14; i++) {
        int idx = tid + i * 256;
        int t = idx / 896;
        int rem = idx - t * 896;
        int row = 64 + (rem >> 4), seg = rem & 15;
        int tok = tok_of(nb, row);
        const __half* g = (t == 0) ? KRh : (t == 1) ? KRl : (t == 2) ? Vh : Vl;
        g += (size_t)tok * DIMC + hh * HDIM + seg * 8;
        cp_async16(sb + t * T2B + row * (T2ST * 2) + seg * 16, g);
    }
    asm volatile("cp.async.commit_group;" ::: "memory");

    // fused ksum + qk while cp.async groups are in flight
    if (tid < HDIM) {
        float a = 0.f;
        for (int p = 0; p < PBLK; p++)
            a += Kbuf[(size_t)tok_of(nb, p) * DIMC + hh * HDIM + tid];
        ksArr[tid] = a;
    }
    __syncthreads();
    if (tid < PBLK) {
        const float* qp = Qbuf + (size_t)tok_of(nb, tid) * DIMC + hh * HDIM;
        float s = 0.f;
#pragma unroll 4
        for (int d = 0; d < HDIM; d++) s += qp[d] * ksArr[d];
        QKbuf[b * PBLK + tid] = s;
    }

    int wid = tid >> 5, lane = tid & 31;
    int q = lane >> 3, rr = lane & 7;
    int wm = (wid & 3) * 32, wn = (wid >> 2) * 64;   // d, e
    uint32_t bKRh = sb, bKRl = sb + T2B, bVh = sb + 2 * T2B, bVl = sb + 3 * T2B;

    float acc[2][8][4];
#pragma unroll
    for (int i = 0; i < 2; i++)
#pragma unroll
        for (int j = 0; j < 8; j++)
#pragma unroll
            for (int r = 0; r < 4; r++) acc[i][j][r] = 0.f;

    asm volatile("cp.async.wait_group 1;" ::: "memory");
    __syncthreads();

#pragma unroll
    for (int ks = 0; ks < 8; ks++) {
        if (ks == 4) {
            asm volatile("cp.async.wait_group 0;" ::: "memory");
            __syncthreads();
        }
        int p0 = ks * 16;
        uint32_t ah[2][4], al[2][4], bh[4][4], bl[4][4];
#pragma unroll
        for (int mt = 0; mt < 2; mt++) {
            int d0 = wm + mt * 16;
            uint32_t ad = (uint32_t)((p0 + (q >> 1) * 8 + rr) * T2ST + d0 + (q & 1) * 8) * 2;
            ldm_x4_t(ah[mt], bKRh + ad);
            ldm_x4_t(al[mt], bKRl + ad);
        }
#pragma unroll
        for (int nt2 = 0; nt2 < 4; nt2++) {
            int e0 = wn + nt2 * 16;
            uint32_t bd = (uint32_t)((p0 + (q & 1) * 8 + rr) * T2ST + e0 + (q >> 1) * 8) * 2;
            ldm_x4_t(bh[nt2], bVh + bd);
            ldm_x4_t(bl[nt2], bVl + bd);
        }
#pragma unroll
        for (int mt = 0; mt < 2; mt++)
#pragma unroll
            for (int nt = 0; nt < 8; nt++) {
                const uint32_t* pbh = &bh[nt >> 1][(nt & 1) * 2];
                const uint32_t* pbl = &bl[nt >> 1][(nt & 1) * 2];
                mma16816(acc[mt][nt], ah[mt], pbh);
                mma16816(acc[mt][nt], ah[mt], pbl);
                mma16816(acc[mt][nt], al[mt], pbh);
            }
    }

    int lr = lane >> 2, lc = lane & 3;
    size_t db = (size_t)b * HDIM * HDIM;
#pragma unroll
    for (int mt = 0; mt < 2; mt++) {
        int d = wm + mt * 16 + lr;
#pragma unroll
        for (int nt = 0; nt < 8; nt++) {
            int e = wn + nt * 8 + lc * 2;
            {
                float v0 = acc[mt][nt][0], v1 = acc[mt][nt][1];
                uint32_t hp = h2pack(v0, v1);
                *(uint32_t*)(KVah + db + d * HDIM + e) = hp;
                *(uint32_t*)(KVal + db + d * HDIM + e) = h2packlo(v0, v1, hp);
            }
            {
                float v0 = acc[mt][nt][2], v1 = acc[mt][nt][3];
                uint32_t hp = h2pack(v0, v1);
                *(uint32_t*)(KVah + db + (d + 8) * HDIM + e) = hp;
                *(uint32_t*)(KVal + db + (d + 8) * HDIM + e) = h2packlo(v0, v1, hp);
            }
        }
    }
}

// ---------------- mix on tensor cores ----------------
#define MXST  168
#define MWB   (160 * MXST * 2)
#define MKST  136
#define MKB   (160 * MKST * 2)
#define MIX2_SMEM (2 * MWB + 2 * MKB)

__global__ __launch_bounds__(256) void mix_tc_kernel() {
    extern __shared__ __align__(16) char smem[];
    uint32_t sb = smem_u32(smem);
    int hh = blockIdx.y, xt = blockIdx.x;
    int tid = threadIdx.x;

    uint32_t bWh = sb, bWl = sb + MWB, bKh = sb + 2 * MWB, bKl = sb + 2 * MWB + MKB;

    for (int i = tid; i < 340; i += 256) {
        int t = i / 170, rem = i % 170;
        int r = rem / 17, s = rem % 17;
        *(uint4*)(smem + 2 * MWB + t * MKB + (150 + r) * (MKST * 2) + s * 16) = make_uint4(0, 0, 0, 0);
    }
#pragma unroll
    for (int i = 0; i < 25; i++) {
        int idx = tid + i * 256;
        int t = idx / 3200, rem = idx % 3200;
        int row = rem / 20, seg = rem % 20;
        const __half* g = ((t == 0) ? WBh : WBl) + row * 160 + seg * 8;
        cp_async16(sb + t * MWB + row * (MXST * 2) + seg * 16, g);
    }
#pragma unroll
    for (int i = 0; i < 19; i++) {
        int idx = tid + i * 256;
        if (idx < 4800) {
            int t = idx / 2400, rem = idx % 2400;
            int row = rem >> 4, seg = rem & 15;
            const __half* g = ((t == 0) ? KVah : KVal)
                            + ((size_t)(hh * NBLK + row)) * (HDIM * HDIM) + xt * 128 + seg * 8;
            cp_async16(sb + 2 * MWB + t * MKB + row * (MKST * 2) + seg * 16, g);
        }
    }
    asm volatile("cp.async.commit_group;" ::: "memory");
    asm volatile("cp.async.wait_group 0;" ::: "memory");
    __syncthreads();

    int wid = tid >> 5, lane = tid & 31;
    int q = lane >> 3, rr = lane & 7;
    int wm = (wid & 1) * 80;
    int wn = (wid >> 1) * 32;

    float acc[5][4][4];
#pragma unroll
    for (int i = 0; i < 5; i++)
#pragma unroll
        for (int j = 0; j < 4; j++)
#pragma unroll
            for (int r = 0; r < 4; r++) acc[i][j][r] = 0.f;

#pragma unroll
    for (int ks = 0; ks < 10; ks++) {
        int k0 = ks * 16;
        uint32_t ah[5][4], al[5][4], bh[2][4], bl[2][4];
#pragma unroll
        for (int mt = 0; mt < 5; mt++) {
            int m0 = wm + mt * 16;
            uint32_t ad = (uint32_t)((m0 + (q & 1) * 8 + rr) * MXST + k0 + (q >> 1) * 8) * 2;
            ldm_x4(ah[mt], bWh + ad);
            ldm_x4(al[mt], bWl + ad);
        }
#pragma unroll
        for (int nt2 = 0; nt2 < 2; nt2++) {
            int e0 = wn + nt2 * 16;
            uint32_t bd = (uint32_t)((k0 + (q & 1) * 8 + rr) * MKST + e0 + (q >> 1) * 8) * 2;
            ldm_x4_t(bh[nt2], bKh + bd);
            ldm_x4_t(bl[nt2], bKl + bd);
        }
#pragma unroll
        for (int mt = 0; mt < 5; mt++)
#pragma unroll
            for (int nt = 0; nt < 4; nt++) {
                const uint32_t* pbh = &bh[nt >> 1][(nt & 1) * 2];
                const uint32_t* pbl = &bl[nt >> 1][(nt & 1) * 2];
                mma16816(acc[mt][nt], ah[mt], pbh);
                mma16816(acc[mt][nt], ah[mt], pbl);
                mma16816(acc[mt][nt], al[mt], pbh);
            }
    }

    int lr = lane >> 2, lc = lane & 3;
#pragma unroll
    for (int mt = 0; mt < 5; mt++) {
        int o = wm + mt * 16 + lr;
#pragma unroll
        for (int half = 0; half < 2; half++) {
            int oo = o + half * 8;
            if (oo < NBLK) {
                size_t gb = ((size_t)(hh * NBLK + oo)) * (HDIM * HDIM) + xt * 128 + wn;
#pragma unroll
                for (int nt = 0; nt < 4; nt++) {
                    int e = nt * 8 + lc * 2;
                    float v0 = acc[mt][nt][2 * half];
                    float v1 = acc[mt][nt][2 * half + 1];
                    uint32_t hp = h2pack(v0, v1);
                    *(uint32_t*)(KVMh + gb + e) = hp;
                    *(uint32_t*)(KVMl + gb + e) = h2packlo(v0, v1, hp);
                }
            }
        }
    }
}

// ---------------- out: tc fp16 3-pass + fused norm; /norm -> AOh ----------------
#define OUT2_SMEM (4 * T2B + 512)

__global__ __launch_bounds__(256) void out_kernel() {
    extern __shared__ __align__(16) char smem[];
    uint32_t sb = smem_u32(smem);
    float* sNorm = (float*)(smem + 4 * T2B);
    int b = blockIdx.x;
    int hh = b / NBLK, nb = b % NBLK;
    int tid = threadIdx.x;

    // group A: QR both tiles (3840) + KVM rows 0..63 (2048) = 5888 segs -> 23/thread
#pragma unroll
    for (int i = 0; i < 23; i++) {
        int idx = tid + i * 256;
        if (idx < 3840) {
            int t = idx / 1920;
            int rem = idx - t * 1920;
            int row = rem >> 4, seg = rem & 15;
            int tok = tok_of(nb, row);
            const __half* g = (t == 0) ? QRh : QRl;
            g += (size_t)tok * DIMC + hh * HDIM + seg * 8;
            cp_async16(sb + t * T2B + row * (T2ST * 2) + seg * 16, g);
        } else if (idx < 5888) {
            int idx2 = idx - 3840;
            int t = idx2 >> 10;
            int rem = idx2 & 1023;
            int row = rem >> 4, seg = rem & 15;
            const __half* g = (t == 0) ? KVMh : KVMl;
            g += (size_t)b * HDIM * HDIM + row * HDIM + seg * 8;
            cp_async16(sb + (2 + t) * T2B + row * (T2ST * 2) + seg * 16, g);
        }
    }
    asm volatile("cp.async.commit_group;" ::: "memory");
    // group B: KVM rows 64..127
#pragma unroll
    for (int i = 0; i < 8; i++) {
        int idx = tid + i * 256;
        int t = idx >> 10;
        int rem = idx & 1023;
        int row = 64 + (rem >> 4), seg = rem & 15;
        const __half* g = (t == 0) ? KVMh : KVMl;
        g += (size_t)b * HDIM * HDIM + row * HDIM + seg * 8;
        cp_async16(sb + (2 + t) * T2B + row * (T2ST * 2) + seg * 16, g);
    }
    asm volatile("cp.async.commit_group;" ::: "memory");

    // fused norm: overlap with in-flight cp.async loads
    if (tid < PBLK) {
        float a = EPSF;
        const float* wrow = WBLKbuf + nb * NBLK;
        const float* qkcol = QKbuf + (size_t)hh * NBLK * PBLK + tid;
        for (int i = 0; i < NBLK; i++)
            a += wrow[i] * qkcol[(size_t)i * PBLK];
        sNorm[tid] = a;
    }

    int wid = tid >> 5, lane = tid & 31;
    int q = lane >> 3, rr = lane & 7;
    int wm = (wid & 1) * 64, wn = (wid >> 1) * 32;   // p, e
    uint32_t bQh = sb, bQl = sb + T2B, bMh = sb + 2 * T2B, bMl = sb + 3 * T2B;

    float acc[4][4][4];
#pragma unroll
    for (int i = 0; i < 4; i++)
#pragma unroll
        for (int j = 0; j < 4; j++)
#pragma unroll
            for (int r = 0; r < 4; r++) acc[i][j][r] = 0.f;

    asm volatile("cp.async.wait_group 1;" ::: "memory");
    __syncthreads();

#pragma unroll
    for (int ks = 0; ks < 8; ks++) {
        if (ks == 4) {
            asm volatile("cp.async.wait_group 0;" ::: "memory");
            __syncthreads();
        }
        int d0 = ks * 16;
        uint32_t ah[4][4], al[4][4], bh[2][4], bl[2][4];
#pragma unroll
        for (int mt = 0; mt < 4; mt++) {
            int m0 = wm + mt * 16;
            uint32_t ad = (uint32_t)((m0 + (q & 1) * 8 + rr) * T2ST + d0 + (q >> 1) * 8) * 2;
            ldm_x4(ah[mt], bQh + ad);
            ldm_x4(al[mt], bQl + ad);
        }
#pragma unroll
        for (int nt2 = 0; nt2 < 2; nt2++) {
            int e0 = wn + nt2 * 16;
            uint32_t bd = (uint32_t)((d0 + (q & 1) * 8 + rr) * T2ST + e0 + (q >> 1) * 8) * 2;
            ldm_x4_t(bh[nt2], bMh + bd);
            ldm_x4_t(bl[nt2], bMl + bd);
        }
#pragma unroll
        for (int mt = 0; mt < 4; mt++)
#pragma unroll
            for (int nt = 0; nt < 4; nt++) {
                const uint32_t* pbh = &bh[nt >> 1][(nt & 1) * 2];
                const uint32_t* pbl = &bl[nt >> 1][(nt & 1) * 2];
                mma16816(acc[mt][nt], ah[mt], pbh);
                mma16816(acc[mt][nt], ah[mt], pbl);
                mma16816(acc[mt][nt], al[mt], pbh);
            }
    }

    int lr = lane >> 2, lc = lane & 3;
#pragma unroll
    for (int mt = 0; mt < 4; mt++) {
        int p = wm + mt * 16 + lr;
#pragma unroll
        for (int half = 0; half < 2; half++) {
            int pp = p + half * 8;
            if (pp < PBLK) {
                float inv = 1.0f / sNorm[pp];
                int tok = tok_of(nb, pp);
                size_t gb = (size_t)tok * DIMC + hh * HDIM;
#pragma unroll
                for (int nt = 0; nt < 4; nt++) {
                    int e = wn + nt * 8 + lc * 2;
                    float v0 = acc[mt][nt][2 * half]     * inv;
                    float v1 = acc[mt][nt][2 * half + 1] * inv;
                    *(uint32_t*)(AOh + gb + e) = h2pack(v0, v1);
                }
            }
        }
    }
}

// ---------------- launch ----------------
extern "C" void kernel_launch(void* const* d_in, const int* in_sizes, int n_in,
                              void* d_out, int out_size) {
    const float* x   = (const float*)d_in[0];
    const float* fc  = (const float*)d_in[3];
    const float* fs  = (const float*)d_in[4];
    const float* wq  = (const float*)d_in[5];
    const float* bq  = (const float*)d_in[6];
    const float* wk  = (const float*)d_in[7];
    const float* bk  = (const float*)d_in[8];
    const float* wv  = (const float*)d_in[9];
    const float* bv  = (const float*)d_in[10];
    const float* wo  = (const float*)d_in[11];
    const float* bo  = (const float*)d_in[12];
    const float* nqw = (const float*)d_in[13];
    const float* nkw = (const float*)d_in[14];
    float* out = (float*)d_out;

    void* pxh;
    cudaGetSymbolAddress(&pxh, Xh);

    cudaFuncSetAttribute(gemm_qkv,  cudaFuncAttributeMaxDynamicSharedMemorySize, GEMM_SMEM);
    cudaFuncSetAttribute(gemm_out,  cudaFuncAttributeMaxDynamicSharedMemorySize, GEMM_SMEM);
    cudaFuncSetAttribute(kv_kernel, cudaFuncAttributeMaxDynamicSharedMemorySize, KV2_SMEM);
    cudaFuncSetAttribute(mix_tc_kernel, cudaFuncAttributeMaxDynamicSharedMemorySize, MIX2_SMEM);
    cudaFuncSetAttribute(out_kernel, cudaFuncAttributeMaxDynamicSharedMemorySize, OUT2_SMEM);

    wblk_kernel<<<NBLK, 256>>>();
    conv_half<<<(MPAD * DIMC) / 256, 256>>>(x, (__half*)pxh, NTOK * DIMC, MPAD * DIMC);
    conv_w4<<<dim3((DIMC * DIMC) / 256, 4), 256>>>(wq, wk, wv, wo);

    dim3 gg(DIMC / 128, MPAD / 128, 3);
    gemm_qkv<<<gg, 256, GEMM_SMEM>>>(bq, bk, bv);

    rmsnorm_rope_kernel<<<dim3(NTOK, 2), 256>>>(nqw, nkw, fc, fs);

    kv_kernel<<<NHEAD * NBLK, 256, KV2_SMEM>>>();
    mix_tc_kernel<<<dim3(128, NHEAD), 256, MIX2_SMEM>>>();
    out_kernel<<<NHEAD * NBLK, 256, OUT2_SMEM>>>();

    dim3 go(DIMC / 128, MPAD / 128);
    gemm_out<<<go, 256, GEMM_SMEM>>>(bo, out);
}

// round 15
// speedup vs baseline: 1.4600x; 1.0288x over previous
#include <cuda_runtime.h>
#include <cuda_fp16.h>
#include <cstdint>
#include <cstdio>

// ---------------- problem dims (fixed) ----------------
#define NTOK   18000      // F*H*W = 12*30*50
#define MPAD   18048      // padded to multiple of 128
#define DIMC   1536
#define NHEAD  12
#define HDIM   128
#define NBLK   150        // FB*HB*WB = 3*5*10
#define PBLK   120        // P1*P2*P3 = 4*6*5
#define EPSF   1e-6f

typedef unsigned long long ull;

// ---------------- mma / ldmatrix helpers ----------------
__device__ __forceinline__ uint32_t smem_u32(const void* p) {
    uint32_t a;
    asm("{ .reg .u64 t; cvta.to.shared.u64 t, %1; cvt.u32.u64 %0, t; }" : "=r"(a) : "l"(p));
    return a;
}
__device__ __forceinline__ void cp_async16(uint32_t dst, const void* src) {
    asm volatile("cp.async.cg.shared.global [%0], [%1], 16;" :: "r"(dst), "l"(src) : "memory");
}
__device__ __forceinline__ void ldm_x4(uint32_t* r, uint32_t addr) {
    asm volatile("ldmatrix.sync.aligned.m8n8.x4.shared.b16 {%0,%1,%2,%3}, [%4];"
                 : "=r"(r[0]), "=r"(r[1]), "=r"(r[2]), "=r"(r[3]) : "r"(addr));
}
__device__ __forceinline__ void ldm_x4_t(uint32_t* r, uint32_t addr) {
    asm volatile("ldmatrix.sync.aligned.m8n8.x4.trans.shared.b16 {%0,%1,%2,%3}, [%4];"
                 : "=r"(r[0]), "=r"(r[1]), "=r"(r[2]), "=r"(r[3]) : "r"(addr));
}
__device__ __forceinline__ void mma16816(float* c, const uint32_t* a, const uint32_t* b) {
    asm volatile("mma.sync.aligned.m16n8k16.row.col.f32.f16.f16.f32 "
                 "{%0,%1,%2,%3}, {%4,%5,%6,%7}, {%8,%9}, {%0,%1,%2,%3};"
                 : "+f"(c[0]), "+f"(c[1]), "+f"(c[2]), "+f"(c[3])
                 : "r"(a[0]), "r"(a[1]), "r"(a[2]), "r"(a[3]), "r"(b[0]), "r"(b[1]));
}
__device__ __forceinline__ uint32_t h2pack(float a, float b) {
    __half2 h = __floats2half2_rn(a, b);
    return *(uint32_t*)&h;
}
__device__ __forceinline__ uint32_t h2packlo(float a, float b, uint32_t hp) {
    __half2 h = *(__half2*)&hp;
    float2 hf = __half22float2(h);
    __half2 l = __floats2half2_rn(a - hf.x, b - hf.y);
    return *(uint32_t*)&l;
}

// ---------------- scratch ----------------
__device__ float Qbuf[NTOK * DIMC];      // raw q proj (fp32, rmsnorm input)
__device__ float Kbuf[NTOK * DIMC];      // raw k proj
__device__ float QKbuf[NHEAD * NBLK * PBLK];
__device__ float WBLKbuf[NBLK * NBLK];

// fp16 operand buffers
__device__ __half Xh[MPAD * DIMC];
__device__ __half AOh[MPAD * DIMC];      // zero-init; pad rows never written
__device__ __half Wh4[4][DIMC * DIMC];
__device__ __half Vh[NTOK * DIMC];
__device__ __half Vl[NTOK * DIMC];
__device__ __half QRh[NTOK * DIMC];
__device__ __half QRl[NTOK * DIMC];
__device__ __half KRh[NTOK * DIMC];
__device__ __half KRl[NTOK * DIMC];
__device__ __half Qph[NTOK * DIMC];      // pre-rope normed q, fp16 (for qk)
__device__ __half Kph[NTOK * DIMC];      // pre-rope normed k, fp16
__device__ __half KVah[NHEAD * NBLK * HDIM * HDIM];
__device__ __half KVal[NHEAD * NBLK * HDIM * HDIM];
__device__ __half KVMh[NHEAD * NBLK * HDIM * HDIM];
__device__ __half KVMl[NHEAD * NBLK * HDIM * HDIM];
__device__ __half WBh[160 * 160];
__device__ __half WBl[160 * 160];

__device__ __forceinline__ int tok_of(int nb, int p) {
    int fb = nb / 50, hb = (nb / 10) % 5, wb = nb % 10;
    int p1 = p / 30, p2 = (p / 5) % 6, p3 = p % 5;
    int f = fb * 4 + p1, h = hb * 6 + p2, w = wb * 5 + p3;
    return (f * 30 + h) * 50 + w;
}

// ---------------- W_BLK ----------------
__global__ void wblk_kernel() {
    int j = blockIdx.x;
    int i = threadIdx.x;
    __shared__ double ssum[256];
    double m = 0.0;
    if (i < NBLK) {
        int fi = i / 50, hi = (i / 10) % 5, wi = i % 10;
        int fj = j / 50, hj = (j / 10) % 5, wj = j % 10;
        double df = fi - fj, dh = hi - hj, dw = wi - wj;
        double d = sqrt(df * df + dh * dh + dw * dw);
        m = 1.0 - d / sqrt(101.0);
    }
    ssum[i] = m;
    __syncthreads();
    for (int s = 128; s > 0; s >>= 1) {
        if (i < s) ssum[i] += ssum[i + s];
        __syncthreads();
    }
    if (i < NBLK) {
        float w = (float)(m / ssum[0]);
        WBLKbuf[i * NBLK + j] = w;
        __half h = __float2half(w);
        WBh[i * 160 + j] = h;
        WBl[i * 160 + j] = __float2half(w - __half2float(h));
    }
}

// ---------------- fp32 -> fp16 ----------------
__global__ void conv_half(const float* __restrict__ src, __half* __restrict__ dst, int n, int ntot) {
    int i = blockIdx.x * 256 + threadIdx.x;
    if (i >= ntot) return;
    float v = (i < n) ? src[i] : 0.f;
    dst[i] = __float2half(v);
}

__global__ void conv_w4(const float* __restrict__ w0, const float* __restrict__ w1,
                        const float* __restrict__ w2, const float* __restrict__ w3) {
    int y = blockIdx.y;
    const float* src = (y == 0) ? w0 : (y == 1) ? w1 : (y == 2) ? w2 : w3;
    int i = blockIdx.x * 256 + threadIdx.x;
    Wh4[y][i] = __float2half(src[i]);
}

// ---------------- pipelined fp16 1-pass tensor-core GEMM ----------------
#define KC      32
#define NCHUNK  (DIMC / KC)              // 48
#define TILEB   (128 * 64)               // 8192 B per operand tile
#define STAGEB  (2 * TILEB)              // 16384 B (A, B)
#define NSTAGE  4
#define GEMM_SMEM (NSTAGE * STAGEB)      // 65536 B -> 2 CTAs/SM

__device__ __forceinline__ void gemm_core(
    const __half* __restrict__ A, const __half* __restrict__ B,
    const float* __restrict__ bias, float* __restrict__ C,
    __half* __restrict__ VhOut, __half* __restrict__ VlOut, int M,
    int m0, int n0, uint32_t sb)
{
    int tid = threadIdx.x;
    int wid = tid >> 5, lane = tid & 31;
    int wm = (wid & 1) * 64;
    int wn = (wid >> 1) * 32;
    int lr = lane >> 2, lc = lane & 3;
    int q = lane >> 3, rr = lane & 7;

    int a_row = (q & 1) * 8 + rr;
    int a_seg0 = q >> 1;
    int b_row = (q >> 1) * 8 + rr;
    int b_seg0 = q & 1;
    int swA = (a_row >> 1) & 3;
    int swB = (b_row >> 1) & 3;
    uint32_t rowbA = (uint32_t)(wm + a_row) * 64;
    uint32_t rowbB = (uint32_t)(wn + b_row) * 64;

    float acc[4][4][4];
#pragma unroll
    for (int i = 0; i < 4; i++)
#pragma unroll
        for (int j = 0; j < 4; j++)
#pragma unroll
            for (int r = 0; r < 4; r++) acc[i][j][r] = 0.f;

    const __half* gptr[4];
    uint32_t sof[4];
#pragma unroll
    for (int i = 0; i < 4; i++) {
        int idx = tid + i * 256;
        int t = idx >> 9, row = (idx >> 2) & 127, seg = idx & 3;
        const __half* g = (t == 0) ? (A + (size_t)(m0 + row) * DIMC + seg * 8)
                                   : (B + (size_t)(n0 + row) * DIMC + seg * 8);
        gptr[i] = g;
        sof[i] = (uint32_t)(t * TILEB + row * 64 + ((seg ^ ((row >> 1) & 3)) * 16));
    }

    auto load_chunk = [&](int c, int st) {
        uint32_t sd = sb + st * STAGEB;
        size_t kof = (size_t)c * KC;
#pragma unroll
        for (int i = 0; i < 4; i++)
            cp_async16(sd + sof[i], gptr[i] + kof);
        asm volatile("cp.async.commit_group;" ::: "memory");
    };

    load_chunk(0, 0);
    load_chunk(1, 1);
    load_chunk(2, 2);
    for (int c = 0; c < NCHUNK; c++) {
        if (c < NCHUNK - 2)
            asm volatile("cp.async.wait_group 2;" ::: "memory");
        else if (c == NCHUNK - 2)
            asm volatile("cp.async.wait_group 1;" ::: "memory");
        else
            asm volatile("cp.async.wait_group 0;" ::: "memory");
        __syncthreads();
        uint32_t tb = sb + (c & 3) * STAGEB;
        uint32_t bA = tb + rowbA;
        uint32_t bB = tb + TILEB + rowbB;

        {
            uint32_t offA = (uint32_t)((a_seg0 ^ swA) * 16);
            uint32_t offB = (uint32_t)((b_seg0 ^ swB) * 16);
            uint32_t ah[4][4], bh[2][4];
#pragma unroll
            for (int mt = 0; mt < 4; mt++)
                ldm_x4(ah[mt], bA + mt * 1024 + offA);
#pragma unroll
            for (int nt2 = 0; nt2 < 2; nt2++)
                ldm_x4(bh[nt2], bB + nt2 * 1024 + offB);
#pragma unroll
            for (int mt = 0; mt < 4; mt++)
#pragma unroll
                for (int nt = 0; nt < 4; nt++)
                    mma16816(acc[mt][nt], ah[mt], &bh[nt >> 1][(nt & 1) * 2]);
        }
        if (c + 3 < NCHUNK) load_chunk(c + 3, (c + 3) & 3);
        {
            uint32_t offA = (uint32_t)(((a_seg0 + 2) ^ swA) * 16);
            uint32_t offB = (uint32_t)(((b_seg0 + 2) ^ swB) * 16);
            uint32_t ah[4][4], bh[2][4];
#pragma unroll
            for (int mt = 0; mt < 4; mt++)
                ldm_x4(ah[mt], bA + mt * 1024 + offA);
#pragma unroll
            for (int nt2 = 0; nt2 < 2; nt2++)
                ldm_x4(bh[nt2], bB + nt2 * 1024 + offB);
#pragma unroll
            for (int mt = 0; mt < 4; mt++)
#pragma unroll
                for (int nt = 0; nt < 4; nt++)
                    mma16816(acc[mt][nt], ah[mt], &bh[nt >> 1][(nt & 1) * 2]);
        }
    }

#pragma unroll
    for (int mt = 0; mt < 4; mt++) {
        int m = m0 + wm + mt * 16 + lr;
#pragma unroll
        for (int nt = 0; nt < 4; nt++) {
            int col = n0 + wn + nt * 8 + lc * 2;
            float bx = bias[col], by = bias[col + 1];
            if (VhOut) {
                if (m < M) {
                    float v0 = acc[mt][nt][0] + bx, v1 = acc[mt][nt][1] + by;
                    uint32_t hp = h2pack(v0, v1);
                    *(uint32_t*)(VhOut + (size_t)m * DIMC + col) = hp;
                    *(uint32_t*)(VlOut + (size_t)m * DIMC + col) = h2packlo(v0, v1, hp);
                }
                if (m + 8 < M) {
                    float v0 = acc[mt][nt][2] + bx, v1 = acc[mt][nt][3] + by;
                    uint32_t hp = h2pack(v0, v1);
                    *(uint32_t*)(VhOut + (size_t)(m + 8) * DIMC + col) = hp;
                    *(uint32_t*)(VlOut + (size_t)(m + 8) * DIMC + col) = h2packlo(v0, v1, hp);
                }
            } else {
                if (m < M) {
                    float2 v = make_float2(acc[mt][nt][0] + bx, acc[mt][nt][1] + by);
                    *(float2*)(C + (size_t)m * DIMC + col) = v;
                }
                if (m + 8 < M) {
                    float2 v = make_float2(acc[mt][nt][2] + bx, acc[mt][nt][3] + by);
                    *(float2*)(C + (size_t)(m + 8) * DIMC + col) = v;
                }
            }
        }
    }
}

__global__ __launch_bounds__(256, 2) void gemm_qkv(
    const float* __restrict__ bq, const float* __restrict__ bk, const float* __restrict__ bv)
{
    extern __shared__ __align__(16) char smem[];
    uint32_t sb = smem_u32(smem);
    int z = blockIdx.z;
    if (z == 2) {
        gemm_core(Xh, Wh4[2], bv, (float*)0, Vh, Vl, NTOK,
                  blockIdx.y * 128, blockIdx.x * 128, sb);
    } else {
        const float* bias = (z == 0) ? bq : bk;
        float* C = (z == 0) ? Qbuf : Kbuf;
        gemm_core(Xh, Wh4[z], bias, C, (__half*)0, (__half*)0, NTOK,
                  blockIdx.y * 128, blockIdx.x * 128, sb);
    }
}

__global__ __launch_bounds__(256, 2) void gemm_out(const float* __restrict__ bo, float* __restrict__ out)
{
    extern __shared__ __align__(16) char smem[];
    uint32_t sb = smem_u32(smem);
    gemm_core(AOh, Wh4[3], bo, out, (__half*)0, (__half*)0, NTOK,
              blockIdx.y * 128, blockIdx.x * 128, sb);
}

// ---------------- fused rmsnorm + relu + eps + RoPE ----------------
// pre-rope -> Qph/Kph fp16 (for qk); roped -> QRh/l, KRh/l. No fp32 writeback.
__global__ void rmsnorm_rope_kernel(const float* __restrict__ nqw, const float* __restrict__ nkw,
                                    const float* __restrict__ fc, const float* __restrict__ fs) {
    int n = blockIdx.x;
    bool isK = blockIdx.y;
    const float* buf = isK ? Kbuf : Qbuf;
    __half* ph = isK ? Kph : Qph;
    __half* rh = isK ? KRh : QRh;
    __half* rl = isK ? KRl : QRl;
    const float* w = isK ? nkw : nqw;
    int tid = threadIdx.x;
    size_t base = (size_t)n * DIMC;
    const float2* b2 = (const float2*)(buf + base);
    const float2* w2 = (const float2*)w;

    int f = n / 1500, rem = n % 1500;
    int hh = rem / 50, ww = rem % 50;

    float2 v[3];
    float ss = 0.f;
#pragma unroll
    for (int t = 0; t < 3; t++) {
        v[t] = b2[tid + t * 256];
        ss += v[t].x * v[t].x + v[t].y * v[t].y;
    }
    for (int o = 16; o > 0; o >>= 1) ss += __shfl_xor_sync(0xffffffffu, ss, o);
    __shared__ float red[8];
    __shared__ float stot;
    if ((tid & 31) == 0) red[tid >> 5] = ss;
    __syncthreads();
    if (tid == 0) {
        float t = 0.f;
        for (int i = 0; i < 8; i++) t += red[i];
        stot = t;
    }
    __syncthreads();
    float sc = 1.0f / sqrtf(stot * (1.0f / DIMC) + EPSF);
#pragma unroll
    for (int t = 0; t < 3; t++) {
        int idx = tid + t * 256;
        float2 wv = w2[idx];
        float x0 = fmaxf(v[t].x * sc * wv.x, 0.f) + EPSF;
        float x1 = fmaxf(v[t].y * sc * wv.y, 0.f) + EPSF;
        *(uint32_t*)(ph + base + 2 * idx) = h2pack(x0, x1);
        int c = idx & 63;
        int pos = (c < 22) ? f : ((c < 43) ? hh : ww);
        float cs = fc[pos * 64 + c];
        float sn = fs[pos * 64 + c];
        float r0 = x0 * cs - x1 * sn;
        float r1 = x0 * sn + x1 * cs;
        uint32_t hp = h2pack(r0, r1);
        *(uint32_t*)(rh + base + 2 * idx) = hp;
        *(uint32_t*)(rl + base + 2 * idx) = h2packlo(r0, r1, hp);
    }
}

// ---------------- fused ksum + qk (fp16 in, fp32 accum) ----------------
__global__ void qk_kernel() {
    int b = blockIdx.x;
    int hh = b / NBLK, nb = b % NBLK;
    int tid = threadIdx.x;
    __shared__ float ks[HDIM];
    float acc = 0.f;
    for (int p = 0; p < PBLK; p++) {
        int t = tok_of(nb, p);
        acc += __half2float(Kph[(size_t)t * DIMC + hh * HDIM + tid]);
    }
    ks[tid] = acc;
    __syncthreads();
    if (tid < PBLK) {
        int t = tok_of(nb, tid);
        const __half* qp = Qph + (size_t)t * DIMC + hh * HDIM;
        float a = 0.f;
#pragma unroll 4
        for (int d = 0; d < HDIM; d++) a += __half2float(qp[d]) * ks[d];
        QKbuf[b * PBLK + tid] = a;
    }
}

// ---------------- kv: tc fp16 3-pass ----------------
#define T2ST  136                       // halves per smem row (272 B, 4-bank rotation)
#define T2B   (128 * T2ST * 2)          // 34816 B per tile
#define KV2_SMEM (4 * T2B)

__global__ __launch_bounds__(256) void kv_kernel() {
    extern __shared__ __align__(16) char smem[];
    uint32_t sb = smem_u32(smem);
    int b = blockIdx.x;
    int hh = b / NBLK, nb = b % NBLK;
    int tid = threadIdx.x;

    // zero k-pad rows 120..127 in all 4 tiles
    for (int i = tid; i < 4 * 8 * 16; i += 256) {
        int t = i >> 7, r = (i >> 4) & 7, s = i & 15;
        *(uint4*)(smem + t * T2B + (120 + r) * (T2ST * 2) + s * 16) = make_uint4(0, 0, 0, 0);
    }
    // group A: rows 0..63 of all 4 tiles
#pragma unroll
    for (int i = 0; i < 16; i++) {
        int idx = tid + i * 256;
        int t = idx >> 10;
        int rem = idx & 1023;
        int row = rem >> 4, seg = rem & 15;
        int tok = tok_of(nb, row);
        const __half* g = (t == 0) ? KRh : (t == 1) ? KRl : (t == 2) ? Vh : Vl;
        g += (size_t)tok * DIMC + hh * HDIM + seg * 8;
        cp_async16(sb + t * T2B + row * (T2ST * 2) + seg * 16, g);
    }
    asm volatile("cp.async.commit_group;" ::: "memory");
    // group B: rows 64..119
#pragma unroll
    for (int i = 0; i < 14; i++) {
        int idx = tid + i * 256;
        int t = idx / 896;
        int rem = idx - t * 896;
        int row = 64 + (rem >> 4), seg = rem & 15;
        int tok = tok_of(nb, row);
        const __half* g = (t == 0) ? KRh : (t == 1) ? KRl : (t == 2) ? Vh : Vl;
        g += (size_t)tok * DIMC + hh * HDIM + seg * 8;
        cp_async16(sb + t * T2B + row * (T2ST * 2) + seg * 16, g);
    }
    asm volatile("cp.async.commit_group;" ::: "memory");

    int wid = tid >> 5, lane = tid & 31;
    int q = lane >> 3, rr = lane & 7;
    int wm = (wid & 3) * 32, wn = (wid >> 2) * 64;   // d, e
    uint32_t bKRh = sb, bKRl = sb + T2B, bVh = sb + 2 * T2B, bVl = sb + 3 * T2B;

    float acc[2][8][4];
#pragma unroll
    for (int i = 0; i < 2; i++)
#pragma unroll
        for (int j = 0; j < 8; j++)
#pragma unroll
            for (int r = 0; r < 4; r++) acc[i][j][r] = 0.f;

    asm volatile("cp.async.wait_group 1;" ::: "memory");
    __syncthreads();

#pragma unroll
    for (int ks = 0; ks < 8; ks++) {
        if (ks == 4) {
            asm volatile("cp.async.wait_group 0;" ::: "memory");
            __syncthreads();
        }
        int p0 = ks * 16;
        uint32_t ah[2][4], al[2][4], bh[4][4], bl[4][4];
#pragma unroll
        for (int mt = 0; mt < 2; mt++) {
            int d0 = wm + mt * 16;
            uint32_t ad = (uint32_t)((p0 + (q >> 1) * 8 + rr) * T2ST + d0 + (q & 1) * 8) * 2;
            ldm_x4_t(ah[mt], bKRh + ad);
            ldm_x4_t(al[mt], bKRl + ad);
        }
#pragma unroll
        for (int nt2 = 0; nt2 < 4; nt2++) {
            int e0 = wn + nt2 * 16;
            uint32_t bd = (uint32_t)((p0 + (q & 1) * 8 + rr) * T2ST + e0 + (q >> 1) * 8) * 2;
            ldm_x4_t(bh[nt2], bVh + bd);
            ldm_x4_t(bl[nt2], bVl + bd);
        }
#pragma unroll
        for (int mt = 0; mt < 2; mt++)
#pragma unroll
            for (int nt = 0; nt < 8; nt++) {
                const uint32_t* pbh = &bh[nt >> 1][(nt & 1) * 2];
                const uint32_t* pbl = &bl[nt >> 1][(nt & 1) * 2];
                mma16816(acc[mt][nt], ah[mt], pbh);
                mma16816(acc[mt][nt], ah[mt], pbl);
                mma16816(acc[mt][nt], al[mt], pbh);
            }
    }

    int lr = lane >> 2, lc = lane & 3;
    size_t db = (size_t)b * HDIM * HDIM;
#pragma unroll
    for (int mt = 0; mt < 2; mt++) {
        int d = wm + mt * 16 + lr;
#pragma unroll
        for (int nt = 0; nt < 8; nt++) {
            int e = wn + nt * 8 + lc * 2;
            {
                float v0 = acc[mt][nt][0], v1 = acc[mt][nt][1];
                uint32_t hp = h2pack(v0, v1);
                *(uint32_t*)(KVah + db + d * HDIM + e) = hp;
                *(uint32_t*)(KVal + db + d * HDIM + e) = h2packlo(v0, v1, hp);
            }
            {
                float v0 = acc[mt][nt][2], v1 = acc[mt][nt][3];
                uint32_t hp = h2pack(v0, v1);
                *(uint32_t*)(KVah + db + (d + 8) * HDIM + e) = hp;
                *(uint32_t*)(KVal + db + (d + 8) * HDIM + e) = h2packlo(v0, v1, hp);
            }
        }
    }
}

// ---------------- mix on tensor cores ----------------
#define MXST  168
#define MWB   (160 * MXST * 2)
#define MKST  136
#define MKB   (160 * MKST * 2)
#define MIX2_SMEM (2 * MWB + 2 * MKB)

__global__ __launch_bounds__(256) void mix_tc_kernel() {
    extern __shared__ __align__(16) char smem[];
    uint32_t sb = smem_u32(smem);
    int hh = blockIdx.y, xt = blockIdx.x;
    int tid = threadIdx.x;

    uint32_t bWh = sb, bWl = sb + MWB, bKh = sb + 2 * MWB, bKl = sb + 2 * MWB + MKB;

    for (int i = tid; i < 340; i += 256) {
        int t = i / 170, rem = i % 170;
        int r = rem / 17, s = rem % 17;
        *(uint4*)(smem + 2 * MWB + t * MKB + (150 + r) * (MKST * 2) + s * 16) = make_uint4(0, 0, 0, 0);
    }
#pragma unroll
    for (int i = 0; i < 25; i++) {
        int idx = tid + i * 256;
        int t = idx / 3200, rem = idx % 3200;
        int row = rem / 20, seg = rem % 20;
        const __half* g = ((t == 0) ? WBh : WBl) + row * 160 + seg * 8;
        cp_async16(sb + t * MWB + row * (MXST * 2) + seg * 16, g);
    }
#pragma unroll
    for (int i = 0; i < 19; i++) {
        int idx = tid + i * 256;
        if (idx < 4800) {
            int t = idx / 2400, rem = idx % 2400;
            int row = rem >> 4, seg = rem & 15;
            const __half* g = ((t == 0) ? KVah : KVal)
                            + ((size_t)(hh * NBLK + row)) * (HDIM * HDIM) + xt * 128 + seg * 8;
            cp_async16(sb + 2 * MWB + t * MKB + row * (MKST * 2) + seg * 16, g);
        }
    }
    asm volatile("cp.async.commit_group;" ::: "memory");
    asm volatile("cp.async.wait_group 0;" ::: "memory");
    __syncthreads();

    int wid = tid >> 5, lane = tid & 31;
    int q = lane >> 3, rr = lane & 7;
    int wm = (wid & 1) * 80;
    int wn = (wid >> 1) * 32;

    float acc[5][4][4];
#pragma unroll
    for (int i = 0; i < 5; i++)
#pragma unroll
        for (int j = 0; j < 4; j++)
#pragma unroll
            for (int r = 0; r < 4; r++) acc[i][j][r] = 0.f;

#pragma unroll
    for (int ks = 0; ks < 10; ks++) {
        int k0 = ks * 16;
        uint32_t ah[5][4], al[5][4], bh[2][4], bl[2][4];
#pragma unroll
        for (int mt = 0; mt < 5; mt++) {
            int m0 = wm + mt * 16;
            uint32_t ad = (uint32_t)((m0 + (q & 1) * 8 + rr) * MXST + k0 + (q >> 1) * 8) * 2;
            ldm_x4(ah[mt], bWh + ad);
            ldm_x4(al[mt], bWl + ad);
        }
#pragma unroll
        for (int nt2 = 0; nt2 < 2; nt2++) {
            int e0 = wn + nt2 * 16;
            uint32_t bd = (uint32_t)((k0 + (q & 1) * 8 + rr) * MKST + e0 + (q >> 1) * 8) * 2;
            ldm_x4_t(bh[nt2], bKh + bd);
            ldm_x4_t(bl[nt2], bKl + bd);
        }
#pragma unroll
        for (int mt = 0; mt < 5; mt++)
#pragma unroll
            for (int nt = 0; nt < 4; nt++) {
                const uint32_t* pbh = &bh[nt >> 1][(nt & 1) * 2];
                const uint32_t* pbl = &bl[nt >> 1][(nt & 1) * 2];
                mma16816(acc[mt][nt], ah[mt], pbh);
                mma16816(acc[mt][nt], ah[mt], pbl);
                mma16816(acc[mt][nt], al[mt], pbh);
            }
    }

    int lr = lane >> 2, lc = lane & 3;
#pragma unroll
    for (int mt = 0; mt < 5; mt++) {
        int o = wm + mt * 16 + lr;
#pragma unroll
        for (int half = 0; half < 2; half++) {
            int oo = o + half * 8;
            if (oo < NBLK) {
                size_t gb = ((size_t)(hh * NBLK + oo)) * (HDIM * HDIM) + xt * 128 + wn;
#pragma unroll
                for (int nt = 0; nt < 4; nt++) {
                    int e = nt * 8 + lc * 2;
                    float v0 = acc[mt][nt][2 * half];
                    float v1 = acc[mt][nt][2 * half + 1];
                    uint32_t hp = h2pack(v0, v1);
                    *(uint32_t*)(KVMh + gb + e) = hp;
                    *(uint32_t*)(KVMl + gb + e) = h2packlo(v0, v1, hp);
                }
            }
        }
    }
}

// ---------------- out: tc fp16 3-pass + fused norm; /norm -> AOh ----------------
#define OUT2_SMEM (4 * T2B + 512)

__global__ __launch_bounds__(256) void out_kernel() {
    extern __shared__ __align__(16) char smem[];
    uint32_t sb = smem_u32(smem);
    float* sNorm = (float*)(smem + 4 * T2B);
    int b = blockIdx.x;
    int hh = b / NBLK, nb = b % NBLK;
    int tid = threadIdx.x;

    // group A: QR both tiles (3840) + KVM rows 0..63 (2048) = 5888 segs -> 23/thread
#pragma unroll
    for (int i = 0; i < 23; i++) {
        int idx = tid + i * 256;
        if (idx < 3840) {
            int t = idx / 1920;
            int rem = idx - t * 1920;
            int row = rem >> 4, seg = rem & 15;
            int tok = tok_of(nb, row);
            const __half* g = (t == 0) ? QRh : QRl;
            g += (size_t)tok * DIMC + hh * HDIM + seg * 8;
            cp_async16(sb + t * T2B + row * (T2ST * 2) + seg * 16, g);
        } else if (idx < 5888) {
            int idx2 = idx - 3840;
            int t = idx2 >> 10;
            int rem = idx2 & 1023;
            int row = rem >> 4, seg = rem & 15;
            const __half* g = (t == 0) ? KVMh : KVMl;
            g += (size_t)b * HDIM * HDIM + row * HDIM + seg * 8;
            cp_async16(sb + (2 + t) * T2B + row * (T2ST * 2) + seg * 16, g);
        }
    }
    asm volatile("cp.async.commit_group;" ::: "memory");
    // group B: KVM rows 64..127
#pragma unroll
    for (int i = 0; i < 8; i++) {
        int idx = tid + i * 256;
        int t = idx >> 10;
        int rem = idx & 1023;
        int row = 64 + (rem >> 4), seg = rem & 15;
        const __half* g = (t == 0) ? KVMh : KVMl;
        g += (size_t)b * HDIM * HDIM + row * HDIM + seg * 8;
        cp_async16(sb + (2 + t) * T2B + row * (T2ST * 2) + seg * 16, g);
    }
    asm volatile("cp.async.commit_group;" ::: "memory");

    // fused norm: overlap with in-flight cp.async loads
    if (tid < PBLK) {
        float a = EPSF;
        const float* wrow = WBLKbuf + nb * NBLK;
        const float* qkcol = QKbuf + (size_t)hh * NBLK * PBLK + tid;
        for (int i = 0; i < NBLK; i++)
            a += wrow[i] * qkcol[(size_t)i * PBLK];
        sNorm[tid] = a;
    }

    int wid = tid >> 5, lane = tid & 31;
    int q = lane >> 3, rr = lane & 7;
    int wm = (wid & 1) * 64, wn = (wid >> 1) * 32;   // p, e
    uint32_t bQh = sb, bQl = sb + T2B, bMh = sb + 2 * T2B, bMl = sb + 3 * T2B;

    float acc[4][4][4];
#pragma unroll
    for (int i = 0; i < 4; i++)
#pragma unroll
        for (int j = 0; j < 4; j++)
#pragma unroll
            for (int r = 0; r < 4; r++) acc[i][j][r] = 0.f;

    asm volatile("cp.async.wait_group 1;" ::: "memory");
    __syncthreads();

#pragma unroll
    for (int ks = 0; ks < 8; ks++) {
        if (ks == 4) {
            asm volatile("cp.async.wait_group 0;" ::: "memory");
            __syncthreads();
        }
        int d0 = ks * 16;
        uint32_t ah[4][4], al[4][4], bh[2][4], bl[2][4];
#pragma unroll
        for (int mt = 0; mt < 4; mt++) {
            int m0 = wm + mt * 16;
            uint32_t ad = (uint32_t)((m0 + (q & 1) * 8 + rr) * T2ST + d0 + (q >> 1) * 8) * 2;
            ldm_x4(ah[mt], bQh + ad);
            ldm_x4(al[mt], bQl + ad);
        }
#pragma unroll
        for (int nt2 = 0; nt2 < 2; nt2++) {
            int e0 = wn + nt2 * 16;
            uint32_t bd = (uint32_t)((d0 + (q & 1) * 8 + rr) * T2ST + e0 + (q >> 1) * 8) * 2;
            ldm_x4_t(bh[nt2], bMh + bd);
            ldm_x4_t(bl[nt2], bMl + bd);
        }
#pragma unroll
        for (int mt = 0; mt < 4; mt++)
#pragma unroll
            for (int nt = 0; nt < 4; nt++) {
                const uint32_t* pbh = &bh[nt >> 1][(nt & 1) * 2];
                const uint32_t* pbl = &bl[nt >> 1][(nt & 1) * 2];
                mma16816(acc[mt][nt], ah[mt], pbh);
                mma16816(acc[mt][nt], ah[mt], pbl);
                mma16816(acc[mt][nt], al[mt], pbh);
            }
    }

    int lr = lane >> 2, lc = lane & 3;
#pragma unroll
    for (int mt = 0; mt < 4; mt++) {
        int p = wm + mt * 16 + lr;
#pragma unroll
        for (int half = 0; half < 2; half++) {
            int pp = p + half * 8;
            if (pp < PBLK) {
                float inv = 1.0f / sNorm[pp];
                int tok = tok_of(nb, pp);
                size_t gb = (size_t)tok * DIMC + hh * HDIM;
#pragma unroll
                for (int nt = 0; nt < 4; nt++) {
                    int e = wn + nt * 8 + lc * 2;
                    float v0 = acc[mt][nt][2 * half]     * inv;
                    float v1 = acc[mt][nt][2 * half + 1] * inv;
                    *(uint32_t*)(AOh + gb + e) = h2pack(v0, v1);
                }
            }
        }
    }
}

// ---------------- launch ----------------
extern "C" void kernel_launch(void* const* d_in, const int* in_sizes, int n_in,
                              void* d_out, int out_size) {
    const float* x   = (const float*)d_in[0];
    const float* fc  = (const float*)d_in[3];
    const float* fs  = (const float*)d_in[4];
    const float* wq  = (const float*)d_in[5];
    const float* bq  = (const float*)d_in[6];
    const float* wk  = (const float*)d_in[7];
    const float* bk  = (const float*)d_in[8];
    const float* wv  = (const float*)d_in[9];
    const float* bv  = (const float*)d_in[10];
    const float* wo  = (const float*)d_in[11];
    const float* bo  = (const float*)d_in[12];
    const float* nqw = (const float*)d_in[13];
    const float* nkw = (const float*)d_in[14];
    float* out = (float*)d_out;

    void* pxh;
    cudaGetSymbolAddress(&pxh, Xh);

    cudaFuncSetAttribute(gemm_qkv,  cudaFuncAttributeMaxDynamicSharedMemorySize, GEMM_SMEM);
    cudaFuncSetAttribute(gemm_out,  cudaFuncAttributeMaxDynamicSharedMemorySize, GEMM_SMEM);
    cudaFuncSetAttribute(kv_kernel, cudaFuncAttributeMaxDynamicSharedMemorySize, KV2_SMEM);
    cudaFuncSetAttribute(mix_tc_kernel, cudaFuncAttributeMaxDynamicSharedMemorySize, MIX2_SMEM);
    cudaFuncSetAttribute(out_kernel, cudaFuncAttributeMaxDynamicSharedMemorySize, OUT2_SMEM);

    wblk_kernel<<<NBLK, 256>>>();
    conv_half<<<(MPAD * DIMC) / 256, 256>>>(x, (__half*)pxh, NTOK * DIMC, MPAD * DIMC);
    conv_w4<<<dim3((DIMC * DIMC) / 256, 4), 256>>>(wq, wk, wv, wo);

    dim3 gg(DIMC / 128, MPAD / 128, 3);
    gemm_qkv<<<gg, 256, GEMM_SMEM>>>(bq, bk, bv);

    rmsnorm_rope_kernel<<<dim3(NTOK, 2), 256>>>(nqw, nkw, fc, fs);

    qk_kernel<<<NHEAD * NBLK, HDIM>>>();
    kv_kernel<<<NHEAD * NBLK, 256, KV2_SMEM>>>();
    mix_tc_kernel<<<dim3(128, NHEAD), 256, MIX2_SMEM>>>();
    out_kernel<<<NHEAD * NBLK, 256, OUT2_SMEM>>>();

    dim3 go(DIMC / 128, MPAD / 128);
    gemm_out<<<go, 256, GEMM_SMEM>>>(bo, out);
}

// round 16
// speedup vs baseline: 1.5801x; 1.0823x over previous
#include <cuda_runtime.h>
#include <cuda_fp16.h>
#include <cstdint>
#include <cstdio>

// ---------------- problem dims (fixed) ----------------
#define NTOK   18000      // F*H*W = 12*30*50
#define MPAD   18048      // padded to multiple of 128
#define DIMC   1536
#define NHEAD  12
#define HDIM   128
#define NBLK   150        // FB*HB*WB = 3*5*10
#define PBLK   120        // P1*P2*P3 = 4*6*5
#define EPSF   1e-6f

typedef unsigned long long ull;

// ---------------- mma / ldmatrix helpers ----------------
__device__ __forceinline__ uint32_t smem_u32(const void* p) {
    uint32_t a;
    asm("{ .reg .u64 t; cvta.to.shared.u64 t, %1; cvt.u32.u64 %0, t; }" : "=r"(a) : "l"(p));
    return a;
}
__device__ __forceinline__ void cp_async16(uint32_t dst, const void* src) {
    asm volatile("cp.async.cg.shared.global [%0], [%1], 16;" :: "r"(dst), "l"(src) : "memory");
}
__device__ __forceinline__ void ldm_x4(uint32_t* r, uint32_t addr) {
    asm volatile("ldmatrix.sync.aligned.m8n8.x4.shared.b16 {%0,%1,%2,%3}, [%4];"
                 : "=r"(r[0]), "=r"(r[1]), "=r"(r[2]), "=r"(r[3]) : "r"(addr));
}
__device__ __forceinline__ void ldm_x4_t(uint32_t* r, uint32_t addr) {
    asm volatile("ldmatrix.sync.aligned.m8n8.x4.trans.shared.b16 {%0,%1,%2,%3}, [%4];"
                 : "=r"(r[0]), "=r"(r[1]), "=r"(r[2]), "=r"(r[3]) : "r"(addr));
}
__device__ __forceinline__ void mma16816(float* c, const uint32_t* a, const uint32_t* b) {
    asm volatile("mma.sync.aligned.m16n8k16.row.col.f32.f16.f16.f32 "
                 "{%0,%1,%2,%3}, {%4,%5,%6,%7}, {%8,%9}, {%0,%1,%2,%3};"
                 : "+f"(c[0]), "+f"(c[1]), "+f"(c[2]), "+f"(c[3])
                 : "r"(a[0]), "r"(a[1]), "r"(a[2]), "r"(a[3]), "r"(b[0]), "r"(b[1]));
}
__device__ __forceinline__ uint32_t h2pack(float a, float b) {
    __half2 h = __floats2half2_rn(a, b);
    return *(uint32_t*)&h;
}
__device__ __forceinline__ uint32_t h2packlo(float a, float b, uint32_t hp) {
    __half2 h = *(__half2*)&hp;
    float2 hf = __half22float2(h);
    __half2 l = __floats2half2_rn(a - hf.x, b - hf.y);
    return *(uint32_t*)&l;
}

// ---------------- scratch ----------------
__device__ float Qbuf[NTOK * DIMC];      // raw q proj (fp32, rmsnorm input)
__device__ float Kbuf[NTOK * DIMC];      // raw k proj
__device__ float QKbuf[NHEAD * NBLK * PBLK];
__device__ float WBLKbuf[NBLK * NBLK];

// fp16 operand buffers
__device__ __half Xh[MPAD * DIMC];
__device__ __half AOh[MPAD * DIMC];      // zero-init; pad rows never written
__device__ __half Wh4[4][DIMC * DIMC];
__device__ __half Vh[NTOK * DIMC];
__device__ __half QRh[NTOK * DIMC];
__device__ __half QRl[NTOK * DIMC];
__device__ __half KRh[NTOK * DIMC];
__device__ __half KRl[NTOK * DIMC];
__device__ __half Qph[NTOK * DIMC];      // pre-rope normed q, fp16 (for qk)
__device__ __half Kph[NTOK * DIMC];      // pre-rope normed k, fp16
__device__ __half KVah[NHEAD * NBLK * HDIM * HDIM];   // kv output, fp16 hi
__device__ __half KVal[NHEAD * NBLK * HDIM * HDIM];   // kv output, fp16 lo
__device__ __half KVMh[NHEAD * NBLK * HDIM * HDIM];
__device__ __half WBh[160 * 160];
__device__ __half WBl[160 * 160];

__device__ __forceinline__ int tok_of(int nb, int p) {
    int fb = nb / 50, hb = (nb / 10) % 5, wb = nb % 10;
    int p1 = p / 30, p2 = (p / 5) % 6, p3 = p % 5;
    int f = fb * 4 + p1, h = hb * 6 + p2, w = wb * 5 + p3;
    return (f * 30 + h) * 50 + w;
}

// ---------------- W_BLK ----------------
__global__ void wblk_kernel() {
    int j = blockIdx.x;
    int i = threadIdx.x;
    __shared__ double ssum[256];
    double m = 0.0;
    if (i < NBLK) {
        int fi = i / 50, hi = (i / 10) % 5, wi = i % 10;
        int fj = j / 50, hj = (j / 10) % 5, wj = j % 10;
        double df = fi - fj, dh = hi - hj, dw = wi - wj;
        double d = sqrt(df * df + dh * dh + dw * dw);
        m = 1.0 - d / sqrt(101.0);
    }
    ssum[i] = m;
    __syncthreads();
    for (int s = 128; s > 0; s >>= 1) {
        if (i < s) ssum[i] += ssum[i + s];
        __syncthreads();
    }
    if (i < NBLK) {
        float w = (float)(m / ssum[0]);
        WBLKbuf[i * NBLK + j] = w;
        __half h = __float2half(w);
        WBh[i * 160 + j] = h;
        WBl[i * 160 + j] = __float2half(w - __half2float(h));
    }
}

// ---------------- fp32 -> fp16 ----------------
__global__ void conv_half(const float* __restrict__ src, __half* __restrict__ dst, int n, int ntot) {
    int i = blockIdx.x * 256 + threadIdx.x;
    if (i >= ntot) return;
    float v = (i < n) ? src[i] : 0.f;
    dst[i] = __float2half(v);
}

__global__ void conv_w4(const float* __restrict__ w0, const float* __restrict__ w1,
                        const float* __restrict__ w2, const float* __restrict__ w3) {
    int y = blockIdx.y;
    const float* src = (y == 0) ? w0 : (y == 1) ? w1 : (y == 2) ? w2 : w3;
    int i = blockIdx.x * 256 + threadIdx.x;
    Wh4[y][i] = __float2half(src[i]);
}

// ---------------- pipelined fp16 1-pass tensor-core GEMM ----------------
#define KC      32
#define NCHUNK  (DIMC / KC)              // 48
#define TILEB   (128 * 64)               // 8192 B per operand tile
#define STAGEB  (2 * TILEB)              // 16384 B (A, B)
#define NSTAGE  4
#define GEMM_SMEM (NSTAGE * STAGEB)      // 65536 B -> 2 CTAs/SM

__device__ __forceinline__ void gemm_core(
    const __half* __restrict__ A, const __half* __restrict__ B,
    const float* __restrict__ bias, float* __restrict__ C,
    __half* __restrict__ HOut, int M,
    int m0, int n0, uint32_t sb)
{
    int tid = threadIdx.x;
    int wid = tid >> 5, lane = tid & 31;
    int wm = (wid & 1) * 64;
    int wn = (wid >> 1) * 32;
    int lr = lane >> 2, lc = lane & 3;
    int q = lane >> 3, rr = lane & 7;

    int a_row = (q & 1) * 8 + rr;
    int a_seg0 = q >> 1;
    int b_row = (q >> 1) * 8 + rr;
    int b_seg0 = q & 1;
    int swA = (a_row >> 1) & 3;
    int swB = (b_row >> 1) & 3;
    uint32_t rowbA = (uint32_t)(wm + a_row) * 64;
    uint32_t rowbB = (uint32_t)(wn + b_row) * 64;

    float acc[4][4][4];
#pragma unroll
    for (int i = 0; i < 4; i++)
#pragma unroll
        for (int j = 0; j < 4; j++)
#pragma unroll
            for (int r = 0; r < 4; r++) acc[i][j][r] = 0.f;

    const __half* gptr[4];
    uint32_t sof[4];
#pragma unroll
    for (int i = 0; i < 4; i++) {
        int idx = tid + i * 256;
        int t = idx >> 9, row = (idx >> 2) & 127, seg = idx & 3;
        const __half* g = (t == 0) ? (A + (size_t)(m0 + row) * DIMC + seg * 8)
                                   : (B + (size_t)(n0 + row) * DIMC + seg * 8);
        gptr[i] = g;
        sof[i] = (uint32_t)(t * TILEB + row * 64 + ((seg ^ ((row >> 1) & 3)) * 16));
    }

    auto load_chunk = [&](int c, int st) {
        uint32_t sd = sb + st * STAGEB;
        size_t kof = (size_t)c * KC;
#pragma unroll
        for (int i = 0; i < 4; i++)
            cp_async16(sd + sof[i], gptr[i] + kof);
        asm volatile("cp.async.commit_group;" ::: "memory");
    };

    load_chunk(0, 0);
    load_chunk(1, 1);
    load_chunk(2, 2);
    for (int c = 0; c < NCHUNK; c++) {
        if (c < NCHUNK - 2)
            asm volatile("cp.async.wait_group 2;" ::: "memory");
        else if (c == NCHUNK - 2)
            asm volatile("cp.async.wait_group 1;" ::: "memory");
        else
            asm volatile("cp.async.wait_group 0;" ::: "memory");
        __syncthreads();
        uint32_t tb = sb + (c & 3) * STAGEB;
        uint32_t bA = tb + rowbA;
        uint32_t bB = tb + TILEB + rowbB;

        {
            uint32_t offA = (uint32_t)((a_seg0 ^ swA) * 16);
            uint32_t offB = (uint32_t)((b_seg0 ^ swB) * 16);
            uint32_t ah[4][4], bh[2][4];
#pragma unroll
            for (int mt = 0; mt < 4; mt++)
                ldm_x4(ah[mt], bA + mt * 1024 + offA);
#pragma unroll
            for (int nt2 = 0; nt2 < 2; nt2++)
                ldm_x4(bh[nt2], bB + nt2 * 1024 + offB);
#pragma unroll
            for (int mt = 0; mt < 4; mt++)
#pragma unroll
                for (int nt = 0; nt < 4; nt++)
                    mma16816(acc[mt][nt], ah[mt], &bh[nt >> 1][(nt & 1) * 2]);
        }
        if (c + 3 < NCHUNK) load_chunk(c + 3, (c + 3) & 3);
        {
            uint32_t offA = (uint32_t)(((a_seg0 + 2) ^ swA) * 16);
            uint32_t offB = (uint32_t)(((b_seg0 + 2) ^ swB) * 16);
            uint32_t ah[4][4], bh[2][4];
#pragma unroll
            for (int mt = 0; mt < 4; mt++)
                ldm_x4(ah[mt], bA + mt * 1024 + offA);
#pragma unroll
            for (int nt2 = 0; nt2 < 2; nt2++)
                ldm_x4(bh[nt2], bB + nt2 * 1024 + offB);
#pragma unroll
            for (int mt = 0; mt < 4; mt++)
#pragma unroll
                for (int nt = 0; nt < 4; nt++)
                    mma16816(acc[mt][nt], ah[mt], &bh[nt >> 1][(nt & 1) * 2]);
        }
    }

#pragma unroll
    for (int mt = 0; mt < 4; mt++) {
        int m = m0 + wm + mt * 16 + lr;
#pragma unroll
        for (int nt = 0; nt < 4; nt++) {
            int col = n0 + wn + nt * 8 + lc * 2;
            float bx = bias[col], by = bias[col + 1];
            if (HOut) {
                if (m < M)
                    *(uint32_t*)(HOut + (size_t)m * DIMC + col) =
                        h2pack(acc[mt][nt][0] + bx, acc[mt][nt][1] + by);
                if (m + 8 < M)
                    *(uint32_t*)(HOut + (size_t)(m + 8) * DIMC + col) =
                        h2pack(acc[mt][nt][2] + bx, acc[mt][nt][3] + by);
            } else {
                if (m < M) {
                    float2 v = make_float2(acc[mt][nt][0] + bx, acc[mt][nt][1] + by);
                    *(float2*)(C + (size_t)m * DIMC + col) = v;
                }
                if (m + 8 < M) {
                    float2 v = make_float2(acc[mt][nt][2] + bx, acc[mt][nt][3] + by);
                    *(float2*)(C + (size_t)(m + 8) * DIMC + col) = v;
                }
            }
        }
    }
}

__global__ __launch_bounds__(256, 2) void gemm_qkv(
    const float* __restrict__ bq, const float* __restrict__ bk, const float* __restrict__ bv)
{
    extern __shared__ __align__(16) char smem[];
    uint32_t sb = smem_u32(smem);
    int z = blockIdx.z;
    if (z == 2) {
        gemm_core(Xh, Wh4[2], bv, (float*)0, Vh, NTOK,
                  blockIdx.y * 128, blockIdx.x * 128, sb);
    } else {
        const float* bias = (z == 0) ? bq : bk;
        float* C = (z == 0) ? Qbuf : Kbuf;
        gemm_core(Xh, Wh4[z], bias, C, (__half*)0, NTOK,
                  blockIdx.y * 128, blockIdx.x * 128, sb);
    }
}

__global__ __launch_bounds__(256, 2) void gemm_out(const float* __restrict__ bo, float* __restrict__ out)
{
    extern __shared__ __align__(16) char smem[];
    uint32_t sb = smem_u32(smem);
    gemm_core(AOh, Wh4[3], bo, out, (__half*)0, NTOK,
              blockIdx.y * 128, blockIdx.x * 128, sb);
}

// ---------------- fused rmsnorm + relu + eps + RoPE ----------------
__global__ void rmsnorm_rope_kernel(const float* __restrict__ nqw, const float* __restrict__ nkw,
                                    const float* __restrict__ fc, const float* __restrict__ fs) {
    int n = blockIdx.x;
    bool isK = blockIdx.y;
    const float* buf = isK ? Kbuf : Qbuf;
    __half* ph = isK ? Kph : Qph;
    __half* rh = isK ? KRh : QRh;
    __half* rl = isK ? KRl : QRl;
    const float* w = isK ? nkw : nqw;
    int tid = threadIdx.x;
    size_t base = (size_t)n * DIMC;
    const float2* b2 = (const float2*)(buf + base);
    const float2* w2 = (const float2*)w;

    int f = n / 1500, rem = n % 1500;
    int hh = rem / 50, ww = rem % 50;

    float2 v[3];
    float ss = 0.f;
#pragma unroll
    for (int t = 0; t < 3; t++) {
        v[t] = b2[tid + t * 256];
        ss += v[t].x * v[t].x + v[t].y * v[t].y;
    }
    for (int o = 16; o > 0; o >>= 1) ss += __shfl_xor_sync(0xffffffffu, ss, o);
    __shared__ float red[8];
    __shared__ float stot;
    if ((tid & 31) == 0) red[tid >> 5] = ss;
    __syncthreads();
    if (tid == 0) {
        float t = 0.f;
        for (int i = 0; i < 8; i++) t += red[i];
        stot = t;
    }
    __syncthreads();
    float sc = 1.0f / sqrtf(stot * (1.0f / DIMC) + EPSF);
#pragma unroll
    for (int t = 0; t < 3; t++) {
        int idx = tid + t * 256;
        float2 wv = w2[idx];
        float x0 = fmaxf(v[t].x * sc * wv.x, 0.f) + EPSF;
        float x1 = fmaxf(v[t].y * sc * wv.y, 0.f) + EPSF;
        *(uint32_t*)(ph + base + 2 * idx) = h2pack(x0, x1);
        int c = idx & 63;
        int pos = (c < 22) ? f : ((c < 43) ? hh : ww);
        float cs = fc[pos * 64 + c];
        float sn = fs[pos * 64 + c];
        float r0 = x0 * cs - x1 * sn;
        float r1 = x0 * sn + x1 * cs;
        uint32_t hp = h2pack(r0, r1);
        *(uint32_t*)(rh + base + 2 * idx) = hp;
        *(uint32_t*)(rl + base + 2 * idx) = h2packlo(r0, r1, hp);
    }
}

// ---------------- fused ksum + qk (fp16 in, fp32 accum) ----------------
__global__ void qk_kernel() {
    int b = blockIdx.x;
    int hh = b / NBLK, nb = b % NBLK;
    int tid = threadIdx.x;
    __shared__ float ks[HDIM];
    float acc = 0.f;
    for (int p = 0; p < PBLK; p++) {
        int t = tok_of(nb, p);
        acc += __half2float(Kph[(size_t)t * DIMC + hh * HDIM + tid]);
    }
    ks[tid] = acc;
    __syncthreads();
    if (tid < PBLK) {
        int t = tok_of(nb, tid);
        const __half* qp = Qph + (size_t)t * DIMC + hh * HDIM;
        float a = 0.f;
#pragma unroll 4
        for (int d = 0; d < HDIM; d++) a += __half2float(qp[d]) * ks[d];
        QKbuf[b * PBLK + tid] = a;
    }
}

// ---------------- kv: tc fp16 2-pass (KRh+KRl)*Vh; 3 tiles -> 2 CTAs/SM ----------------
#define T2ST  136                       // halves per smem row (272 B, 4-bank rotation)
#define T2B   (128 * T2ST * 2)          // 34816 B per tile
#define KV2_SMEM (3 * T2B)              // 104448 -> 2 CTAs/SM

__global__ __launch_bounds__(256, 2) void kv_kernel() {
    extern __shared__ __align__(16) char smem[];
    uint32_t sb = smem_u32(smem);
    int b = blockIdx.x;
    int hh = b / NBLK, nb = b % NBLK;
    int tid = threadIdx.x;

    // zero p-pad rows 120..127 in all 3 tiles
    for (int i = tid; i < 3 * 8 * 16; i += 256) {
        int t = i >> 7, r = (i >> 4) & 7, s = i & 15;
        *(uint4*)(smem + t * T2B + (120 + r) * (T2ST * 2) + s * 16) = make_uint4(0, 0, 0, 0);
    }
    // group A: rows 0..63 of 3 tiles (3072 segs -> 12/thread)
#pragma unroll
    for (int i = 0; i < 12; i++) {
        int idx = tid + i * 256;
        int t = idx >> 10;
        int rem = idx & 1023;
        int row = rem >> 4, seg = rem & 15;
        int tok = tok_of(nb, row);
        const __half* g = (t == 0) ? KRh : (t == 1) ? KRl : Vh;
        g += (size_t)tok * DIMC + hh * HDIM + seg * 8;
        cp_async16(sb + t * T2B + row * (T2ST * 2) + seg * 16, g);
    }
    asm volatile("cp.async.commit_group;" ::: "memory");
    // group B: rows 64..119 (3*896 = 2688 segs -> 11/thread w/ guard)
#pragma unroll
    for (int i = 0; i < 11; i++) {
        int idx = tid + i * 256;
        if (idx < 2688) {
            int t = idx / 896;
            int rem = idx - t * 896;
            int row = 64 + (rem >> 4), seg = rem & 15;
            int tok = tok_of(nb, row);
            const __half* g = (t == 0) ? KRh : (t == 1) ? KRl : Vh;
            g += (size_t)tok * DIMC + hh * HDIM + seg * 8;
            cp_async16(sb + t * T2B + row * (T2ST * 2) + seg * 16, g);
        }
    }
    asm volatile("cp.async.commit_group;" ::: "memory");

    int wid = tid >> 5, lane = tid & 31;
    int q = lane >> 3, rr = lane & 7;
    int wm = (wid & 3) * 32, wn = (wid >> 2) * 64;   // d, e
    uint32_t bKRh = sb, bKRl = sb + T2B, bVh = sb + 2 * T2B;

    float acc[2][8][4];
#pragma unroll
    for (int i = 0; i < 2; i++)
#pragma unroll
        for (int j = 0; j < 8; j++)
#pragma unroll
            for (int r = 0; r < 4; r++) acc[i][j][r] = 0.f;

    asm volatile("cp.async.wait_group 1;" ::: "memory");
    __syncthreads();

#pragma unroll
    for (int ks = 0; ks < 8; ks++) {
        if (ks == 4) {
            asm volatile("cp.async.wait_group 0;" ::: "memory");
            __syncthreads();
        }
        int p0 = ks * 16;
        uint32_t ah[2][4], al[2][4], bh[4][4];
#pragma unroll
        for (int mt = 0; mt < 2; mt++) {
            int d0 = wm + mt * 16;
            uint32_t ad = (uint32_t)((p0 + (q >> 1) * 8 + rr) * T2ST + d0 + (q & 1) * 8) * 2;
            ldm_x4_t(ah[mt], bKRh + ad);
            ldm_x4_t(al[mt], bKRl + ad);
        }
#pragma unroll
        for (int nt2 = 0; nt2 < 4; nt2++) {
            int e0 = wn + nt2 * 16;
            uint32_t bd = (uint32_t)((p0 + (q & 1) * 8 + rr) * T2ST + e0 + (q >> 1) * 8) * 2;
            ldm_x4_t(bh[nt2], bVh + bd);
        }
#pragma unroll
        for (int mt = 0; mt < 2; mt++)
#pragma unroll
            for (int nt = 0; nt < 8; nt++) {
                const uint32_t* pbh = &bh[nt >> 1][(nt & 1) * 2];
                mma16816(acc[mt][nt], ah[mt], pbh);
                mma16816(acc[mt][nt], al[mt], pbh);
            }
    }

    int lr = lane >> 2, lc = lane & 3;
    size_t db = (size_t)b * HDIM * HDIM;
#pragma unroll
    for (int mt = 0; mt < 2; mt++) {
        int d = wm + mt * 16 + lr;
#pragma unroll
        for (int nt = 0; nt < 8; nt++) {
            int e = wn + nt * 8 + lc * 2;
            {
                float v0 = acc[mt][nt][0], v1 = acc[mt][nt][1];
                uint32_t hp = h2pack(v0, v1);
                *(uint32_t*)(KVah + db + d * HDIM + e) = hp;
                *(uint32_t*)(KVal + db + d * HDIM + e) = h2packlo(v0, v1, hp);
            }
            {
                float v0 = acc[mt][nt][2], v1 = acc[mt][nt][3];
                uint32_t hp = h2pack(v0, v1);
                *(uint32_t*)(KVah + db + (d + 8) * HDIM + e) = hp;
                *(uint32_t*)(KVal + db + (d + 8) * HDIM + e) = h2packlo(v0, v1, hp);
            }
        }
    }
}

// ---------------- mix on tensor cores (3-pass, writes KVMh only) ----------------
#define MXST  168
#define MWB   (160 * MXST * 2)
#define MKST  136
#define MKB   (160 * MKST * 2)
#define MIX2_SMEM (2 * MWB + 2 * MKB)

__global__ __launch_bounds__(256) void mix_tc_kernel() {
    extern __shared__ __align__(16) char smem[];
    uint32_t sb = smem_u32(smem);
    int hh = blockIdx.y, xt = blockIdx.x;
    int tid = threadIdx.x;

    uint32_t bWh = sb, bWl = sb + MWB, bKh = sb + 2 * MWB, bKl = sb + 2 * MWB + MKB;

    for (int i = tid; i < 340; i += 256) {
        int t = i / 170, rem = i % 170;
        int r = rem / 17, s = rem % 17;
        *(uint4*)(smem + 2 * MWB + t * MKB + (150 + r) * (MKST * 2) + s * 16) = make_uint4(0, 0, 0, 0);
    }
#pragma unroll
    for (int i = 0; i < 25; i++) {
        int idx = tid + i * 256;
        int t = idx / 3200, rem = idx % 3200;
        int row = rem / 20, seg = rem % 20;
        const __half* g = ((t == 0) ? WBh : WBl) + row * 160 + seg * 8;
        cp_async16(sb + t * MWB + row * (MXST * 2) + seg * 16, g);
    }
#pragma unroll
    for (int i = 0; i < 19; i++) {
        int idx = tid + i * 256;
        if (idx < 4800) {
            int t = idx / 2400, rem = idx % 2400;
            int row = rem >> 4, seg = rem & 15;
            const __half* g = ((t == 0) ? KVah : KVal)
                            + ((size_t)(hh * NBLK + row)) * (HDIM * HDIM) + xt * 128 + seg * 8;
            cp_async16(sb + 2 * MWB + t * MKB + row * (MKST * 2) + seg * 16, g);
        }
    }
    asm volatile("cp.async.commit_group;" ::: "memory");
    asm volatile("cp.async.wait_group 0;" ::: "memory");
    __syncthreads();

    int wid = tid >> 5, lane = tid & 31;
    int q = lane >> 3, rr = lane & 7;
    int wm = (wid & 1) * 80;
    int wn = (wid >> 1) * 32;

    float acc[5][4][4];
#pragma unroll
    for (int i = 0; i < 5; i++)
#pragma unroll
        for (int j = 0; j < 4; j++)
#pragma unroll
            for (int r = 0; r < 4; r++) acc[i][j][r] = 0.f;

#pragma unroll
    for (int ks = 0; ks < 10; ks++) {
        int k0 = ks * 16;
        uint32_t ah[5][4], al[5][4], bh[2][4], bl[2][4];
#pragma unroll
        for (int mt = 0; mt < 5; mt++) {
            int m0 = wm + mt * 16;
            uint32_t ad = (uint32_t)((m0 + (q & 1) * 8 + rr) * MXST + k0 + (q >> 1) * 8) * 2;
            ldm_x4(ah[mt], bWh + ad);
            ldm_x4(al[mt], bWl + ad);
        }
#pragma unroll
        for (int nt2 = 0; nt2 < 2; nt2++) {
            int e0 = wn + nt2 * 16;
            uint32_t bd = (uint32_t)((k0 + (q & 1) * 8 + rr) * MKST + e0 + (q >> 1) * 8) * 2;
            ldm_x4_t(bh[nt2], bKh + bd);
            ldm_x4_t(bl[nt2], bKl + bd);
        }
#pragma unroll
        for (int mt = 0; mt < 5; mt++)
#pragma unroll
            for (int nt = 0; nt < 4; nt++) {
                const uint32_t* pbh = &bh[nt >> 1][(nt & 1) * 2];
                const uint32_t* pbl = &bl[nt >> 1][(nt & 1) * 2];
                mma16816(acc[mt][nt], ah[mt], pbh);
                mma16816(acc[mt][nt], ah[mt], pbl);
                mma16816(acc[mt][nt], al[mt], pbh);
            }
    }

    int lr = lane >> 2, lc = lane & 3;
#pragma unroll
    for (int mt = 0; mt < 5; mt++) {
        int o = wm + mt * 16 + lr;
#pragma unroll
        for (int half = 0; half < 2; half++) {
            int oo = o + half * 8;
            if (oo < NBLK) {
                size_t gb = ((size_t)(hh * NBLK + oo)) * (HDIM * HDIM) + xt * 128 + wn;
#pragma unroll
                for (int nt = 0; nt < 4; nt++) {
                    int e = nt * 8 + lc * 2;
                    *(uint32_t*)(KVMh + gb + e) =
                        h2pack(acc[mt][nt][2 * half], acc[mt][nt][2 * half + 1]);
                }
            }
        }
    }
}

// ---------------- out: tc fp16 2-pass (QRh+QRl)*KVMh + fused norm; 3 tiles -> 2 CTAs/SM ----------------
#define OUT2_SMEM (3 * T2B + 512)

__global__ __launch_bounds__(256, 2) void out_kernel() {
    extern __shared__ __align__(16) char smem[];
    uint32_t sb = smem_u32(smem);
    float* sNorm = (float*)(smem + 3 * T2B);
    int b = blockIdx.x;
    int hh = b / NBLK, nb = b % NBLK;
    int tid = threadIdx.x;

    // zero QR pad rows 120..127 (2 tiles)
    for (int i = tid; i < 256; i += 256) {
        int t = i >> 7, r = (i >> 4) & 7, s = i & 15;
        *(uint4*)(smem + t * T2B + (120 + r) * (T2ST * 2) + s * 16) = make_uint4(0, 0, 0, 0);
    }
    // group A: QR both tiles (3840) + KVMh rows 0..63 (1024) = 4864 -> 19/thread exact
#pragma unroll
    for (int i = 0; i < 19; i++) {
        int idx = tid + i * 256;
        if (idx < 3840) {
            int t = idx / 1920;
            int rem = idx - t * 1920;
            int row = rem >> 4, seg = rem & 15;
            int tok = tok_of(nb, row);
            const __half* g = (t == 0) ? QRh : QRl;
            g += (size_t)tok * DIMC + hh * HDIM + seg * 8;
            cp_async16(sb + t * T2B + row * (T2ST * 2) + seg * 16, g);
        } else {
            int idx2 = idx - 3840;
            int row = idx2 >> 4, seg = idx2 & 15;
            const __half* g = KVMh + (size_t)b * HDIM * HDIM + row * HDIM + seg * 8;
            cp_async16(sb + 2 * T2B + row * (T2ST * 2) + seg * 16, g);
        }
    }
    asm volatile("cp.async.commit_group;" ::: "memory");
    // group B: KVMh rows 64..127 (1024 segs -> 4/thread)
#pragma unroll
    for (int i = 0; i < 4; i++) {
        int idx = tid + i * 256;
        int row = 64 + (idx >> 4), seg = idx & 15;
        const __half* g = KVMh + (size_t)b * HDIM * HDIM + row * HDIM + seg * 8;
        cp_async16(sb + 2 * T2B + row * (T2ST * 2) + seg * 16, g);
    }
    asm volatile("cp.async.commit_group;" ::: "memory");

    // fused norm: overlap with in-flight cp.async loads
    if (tid < PBLK) {
        float a = EPSF;
        const float* wrow = WBLKbuf + nb * NBLK;
        const float* qkcol = QKbuf + (size_t)hh * NBLK * PBLK + tid;
        for (int i = 0; i < NBLK; i++)
            a += wrow[i] * qkcol[(size_t)i * PBLK];
        sNorm[tid] = a;
    }

    int wid = tid >> 5, lane = tid & 31;
    int q = lane >> 3, rr = lane & 7;
    int wm = (wid & 1) * 64, wn = (wid >> 1) * 32;   // p, e
    uint32_t bQh = sb, bQl = sb + T2B, bMh = sb + 2 * T2B;

    float acc[4][4][4];
#pragma unroll
    for (int i = 0; i < 4; i++)
#pragma unroll
        for (int j = 0; j < 4; j++)
#pragma unroll
            for (int r = 0; r < 4; r++) acc[i][j][r] = 0.f;

    asm volatile("cp.async.wait_group 1;" ::: "memory");
    __syncthreads();

#pragma unroll
    for (int ks = 0; ks < 8; ks++) {
        if (ks == 4) {
            asm volatile("cp.async.wait_group 0;" ::: "memory");
            __syncthreads();
        }
        int d0 = ks * 16;
        uint32_t ah[4][4], al[4][4], bh[2][4];
#pragma unroll
        for (int mt = 0; mt < 4; mt++) {
            int m0 = wm + mt * 16;
            uint32_t ad = (uint32_t)((m0 + (q & 1) * 8 + rr) * T2ST + d0 + (q >> 1) * 8) * 2;
            ldm_x4(ah[mt], bQh + ad);
            ldm_x4(al[mt], bQl + ad);
        }
#pragma unroll
        for (int nt2 = 0; nt2 < 2; nt2++) {
            int e0 = wn + nt2 * 16;
            uint32_t bd = (uint32_t)((d0 + (q & 1) * 8 + rr) * T2ST + e0 + (q >> 1) * 8) * 2;
            ldm_x4_t(bh[nt2], bMh + bd);
        }
#pragma unroll
        for (int mt = 0; mt < 4; mt++)
#pragma unroll
            for (int nt = 0; nt < 4; nt++) {
                const uint32_t* pbh = &bh[nt >> 1][(nt & 1) * 2];
                mma16816(acc[mt][nt], ah[mt], pbh);
                mma16816(acc[mt][nt], al[mt], pbh);
            }
    }

    int lr = lane >> 2, lc = lane & 3;
#pragma unroll
    for (int mt = 0; mt < 4; mt++) {
        int p = wm + mt * 16 + lr;
#pragma unroll
        for (int half = 0; half < 2; half++) {
            int pp = p + half * 8;
            if (pp < PBLK) {
                float inv = 1.0f / sNorm[pp];
                int tok = tok_of(nb, pp);
                size_t gb = (size_t)tok * DIMC + hh * HDIM;
#pragma unroll
                for (int nt = 0; nt < 4; nt++) {
                    int e = wn + nt * 8 + lc * 2;
                    float v0 = acc[mt][nt][2 * half]     * inv;
                    float v1 = acc[mt][nt][2 * half + 1] * inv;
                    *(uint32_t*)(AOh + gb + e) = h2pack(v0, v1);
                }
            }
        }
    }
}

// ---------------- launch ----------------
extern "C" void kernel_launch(void* const* d_in, const int* in_sizes, int n_in,
                              void* d_out, int out_size) {
    const float* x   = (const float*)d_in[0];
    const float* fc  = (const float*)d_in[3];
    const float* fs  = (const float*)d_in[4];
    const float* wq  = (const float*)d_in[5];
    const float* bq  = (const float*)d_in[6];
    const float* wk  = (const float*)d_in[7];
    const float* bk  = (const float*)d_in[8];
    const float* wv  = (const float*)d_in[9];
    const float* bv  = (const float*)d_in[10];
    const float* wo  = (const float*)d_in[11];
    const float* bo  = (const float*)d_in[12];
    const float* nqw = (const float*)d_in[13];
    const float* nkw = (const float*)d_in[14];
    float* out = (float*)d_out;

    void* pxh;
    cudaGetSymbolAddress(&pxh, Xh);

    cudaFuncSetAttribute(gemm_qkv,  cudaFuncAttributeMaxDynamicSharedMemorySize, GEMM_SMEM);
    cudaFuncSetAttribute(gemm_out,  cudaFuncAttributeMaxDynamicSharedMemorySize, GEMM_SMEM);
    cudaFuncSetAttribute(kv_kernel, cudaFuncAttributeMaxDynamicSharedMemorySize, KV2_SMEM);
    cudaFuncSetAttribute(mix_tc_kernel, cudaFuncAttributeMaxDynamicSharedMemorySize, MIX2_SMEM);
    cudaFuncSetAttribute(out_kernel, cudaFuncAttributeMaxDynamicSharedMemorySize, OUT2_SMEM);

    wblk_kernel<<<NBLK, 256>>>();
    conv_half<<<(MPAD * DIMC) / 256, 256>>>(x, (__half*)pxh, NTOK * DIMC, MPAD * DIMC);
    conv_w4<<<dim3((DIMC * DIMC) / 256, 4), 256>>>(wq, wk, wv, wo);

    dim3 gg(DIMC / 128, MPAD / 128, 3);
    gemm_qkv<<<gg, 256, GEMM_SMEM>>>(bq, bk, bv);

    rmsnorm_rope_kernel<<<dim3(NTOK, 2), 256>>>(nqw, nkw, fc, fs);

    qk_kernel<<<NHEAD * NBLK, HDIM>>>();
    kv_kernel<<<NHEAD * NBLK, 256, KV2_SMEM>>>();
    mix_tc_kernel<<<dim3(128, NHEAD), 256, MIX2_SMEM>>>();
    out_kernel<<<NHEAD * NBLK, 256, OUT2_SMEM>>>();

    dim3 go(DIMC / 128, MPAD / 128);
    gemm_out<<<go, 256, GEMM_SMEM>>>(bo, out);
}

// round 17
// speedup vs baseline: 1.6340x; 1.0341x over previous
#include <cuda_runtime.h>
#include <cuda_fp16.h>
#include <cstdint>
#include <cstdio>

// ---------------- problem dims (fixed) ----------------
#define NTOK   18000      // F*H*W = 12*30*50
#define MPAD   18048      // padded to multiple of 128
#define DIMC   1536
#define NHEAD  12
#define HDIM   128
#define NBLK   150        // FB*HB*WB = 3*5*10
#define PBLK   120        // P1*P2*P3 = 4*6*5
#define EPSF   1e-6f

typedef unsigned long long ull;

// ---------------- mma / ldmatrix helpers ----------------
__device__ __forceinline__ uint32_t smem_u32(const void* p) {
    uint32_t a;
    asm("{ .reg .u64 t; cvta.to.shared.u64 t, %1; cvt.u32.u64 %0, t; }" : "=r"(a) : "l"(p));
    return a;
}
__device__ __forceinline__ void cp_async16(uint32_t dst, const void* src) {
    asm volatile("cp.async.cg.shared.global [%0], [%1], 16;" :: "r"(dst), "l"(src) : "memory");
}
__device__ __forceinline__ void ldm_x4(uint32_t* r, uint32_t addr) {
    asm volatile("ldmatrix.sync.aligned.m8n8.x4.shared.b16 {%0,%1,%2,%3}, [%4];"
                 : "=r"(r[0]), "=r"(r[1]), "=r"(r[2]), "=r"(r[3]) : "r"(addr));
}
__device__ __forceinline__ void ldm_x4_t(uint32_t* r, uint32_t addr) {
    asm volatile("ldmatrix.sync.aligned.m8n8.x4.trans.shared.b16 {%0,%1,%2,%3}, [%4];"
                 : "=r"(r[0]), "=r"(r[1]), "=r"(r[2]), "=r"(r[3]) : "r"(addr));
}
__device__ __forceinline__ void mma16816(float* c, const uint32_t* a, const uint32_t* b) {
    asm volatile("mma.sync.aligned.m16n8k16.row.col.f32.f16.f16.f32 "
                 "{%0,%1,%2,%3}, {%4,%5,%6,%7}, {%8,%9}, {%0,%1,%2,%3};"
                 : "+f"(c[0]), "+f"(c[1]), "+f"(c[2]), "+f"(c[3])
                 : "r"(a[0]), "r"(a[1]), "r"(a[2]), "r"(a[3]), "r"(b[0]), "r"(b[1]));
}
__device__ __forceinline__ uint32_t h2pack(float a, float b) {
    __half2 h = __floats2half2_rn(a, b);
    return *(uint32_t*)&h;
}
__device__ __forceinline__ uint32_t h2packlo(float a, float b, uint32_t hp) {
    __half2 h = *(__half2*)&hp;
    float2 hf = __half22float2(h);
    __half2 l = __floats2half2_rn(a - hf.x, b - hf.y);
    return *(uint32_t*)&l;
}

// ---------------- scratch ----------------
__device__ float Qbuf[NTOK * DIMC];      // raw q proj (fp32, rmsnorm input)
__device__ float Kbuf[NTOK * DIMC];      // raw k proj
__device__ float QKbuf[NHEAD * NBLK * PBLK];
__device__ float WBLKbuf[NBLK * NBLK];

// fp16 operand buffers
__device__ __half Xh[MPAD * DIMC];
__device__ __half AOh[MPAD * DIMC];      // zero-init; pad rows never written
__device__ __half Wh4[4][DIMC * DIMC];
__device__ __half Vh[NTOK * DIMC];
__device__ __half QRh[NTOK * DIMC];
__device__ __half KRh[NTOK * DIMC];
__device__ __half Qph[NTOK * DIMC];      // pre-rope normed q, fp16 (for qk)
__device__ __half Kph[NTOK * DIMC];      // pre-rope normed k, fp16
__device__ __half KVah[NHEAD * NBLK * HDIM * HDIM];   // kv output, fp16 hi
__device__ __half KVal[NHEAD * NBLK * HDIM * HDIM];   // kv output, fp16 lo
__device__ __half KVMh[NHEAD * NBLK * HDIM * HDIM];
__device__ __half WBh[160 * 160];
__device__ __half WBl[160 * 160];

__device__ __forceinline__ int tok_of(int nb, int p) {
    int fb = nb / 50, hb = (nb / 10) % 5, wb = nb % 10;
    int p1 = p / 30, p2 = (p / 5) % 6, p3 = p % 5;
    int f = fb * 4 + p1, h = hb * 6 + p2, w = wb * 5 + p3;
    return (f * 30 + h) * 50 + w;
}

// ---------------- W_BLK ----------------
__global__ void wblk_kernel() {
    int j = blockIdx.x;
    int i = threadIdx.x;
    __shared__ double ssum[256];
    double m = 0.0;
    if (i < NBLK) {
        int fi = i / 50, hi = (i / 10) % 5, wi = i % 10;
        int fj = j / 50, hj = (j / 10) % 5, wj = j % 10;
        double df = fi - fj, dh = hi - hj, dw = wi - wj;
        double d = sqrt(df * df + dh * dh + dw * dw);
        m = 1.0 - d / sqrt(101.0);
    }
    ssum[i] = m;
    __syncthreads();
    for (int s = 128; s > 0; s >>= 1) {
        if (i < s) ssum[i] += ssum[i + s];
        __syncthreads();
    }
    if (i < NBLK) {
        float w = (float)(m / ssum[0]);
        WBLKbuf[i * NBLK + j] = w;
        __half h = __float2half(w);
        WBh[i * 160 + j] = h;
        WBl[i * 160 + j] = __float2half(w - __half2float(h));
    }
}

// ---------------- fp32 -> fp16 ----------------
__global__ void conv_half(const float* __restrict__ src, __half* __restrict__ dst, int n, int ntot) {
    int i = blockIdx.x * 256 + threadIdx.x;
    if (i >= ntot) return;
    float v = (i < n) ? src[i] : 0.f;
    dst[i] = __float2half(v);
}

__global__ void conv_w4(const float* __restrict__ w0, const float* __restrict__ w1,
                        const float* __restrict__ w2, const float* __restrict__ w3) {
    int y = blockIdx.y;
    const float* src = (y == 0) ? w0 : (y == 1) ? w1 : (y == 2) ? w2 : w3;
    int i = blockIdx.x * 256 + threadIdx.x;
    Wh4[y][i] = __float2half(src[i]);
}

// ---------------- pipelined fp16 1-pass tensor-core GEMM ----------------
#define KC      32
#define NCHUNK  (DIMC / KC)              // 48
#define TILEB   (128 * 64)               // 8192 B per operand tile
#define STAGEB  (2 * TILEB)              // 16384 B (A, B)
#define NSTAGE  4
#define GEMM_SMEM (NSTAGE * STAGEB)      // 65536 B -> 2 CTAs/SM

__device__ __forceinline__ void gemm_core(
    const __half* __restrict__ A, const __half* __restrict__ B,
    const float* __restrict__ bias, float* __restrict__ C,
    __half* __restrict__ HOut, int M,
    int m0, int n0, uint32_t sb)
{
    int tid = threadIdx.x;
    int wid = tid >> 5, lane = tid & 31;
    int wm = (wid & 1) * 64;
    int wn = (wid >> 1) * 32;
    int lr = lane >> 2, lc = lane & 3;
    int q = lane >> 3, rr = lane & 7;

    int a_row = (q & 1) * 8 + rr;
    int a_seg0 = q >> 1;
    int b_row = (q >> 1) * 8 + rr;
    int b_seg0 = q & 1;
    int swA = (a_row >> 1) & 3;
    int swB = (b_row >> 1) & 3;
    uint32_t rowbA = (uint32_t)(wm + a_row) * 64;
    uint32_t rowbB = (uint32_t)(wn + b_row) * 64;

    float acc[4][4][4];
#pragma unroll
    for (int i = 0; i < 4; i++)
#pragma unroll
        for (int j = 0; j < 4; j++)
#pragma unroll
            for (int r = 0; r < 4; r++) acc[i][j][r] = 0.f;

    const __half* gptr[4];
    uint32_t sof[4];
#pragma unroll
    for (int i = 0; i < 4; i++) {
        int idx = tid + i * 256;
        int t = idx >> 9, row = (idx >> 2) & 127, seg = idx & 3;
        const __half* g = (t == 0) ? (A + (size_t)(m0 + row) * DIMC + seg * 8)
                                   : (B + (size_t)(n0 + row) * DIMC + seg * 8);
        gptr[i] = g;
        sof[i] = (uint32_t)(t * TILEB + row * 64 + ((seg ^ ((row >> 1) & 3)) * 16));
    }

    auto load_chunk = [&](int c, int st) {
        uint32_t sd = sb + st * STAGEB;
        size_t kof = (size_t)c * KC;
#pragma unroll
        for (int i = 0; i < 4; i++)
            cp_async16(sd + sof[i], gptr[i] + kof);
        asm volatile("cp.async.commit_group;" ::: "memory");
    };

    load_chunk(0, 0);
    load_chunk(1, 1);
    load_chunk(2, 2);
    for (int c = 0; c < NCHUNK; c++) {
        if (c < NCHUNK - 2)
            asm volatile("cp.async.wait_group 2;" ::: "memory");
        else if (c == NCHUNK - 2)
            asm volatile("cp.async.wait_group 1;" ::: "memory");
        else
            asm volatile("cp.async.wait_group 0;" ::: "memory");
        __syncthreads();
        uint32_t tb = sb + (c & 3) * STAGEB;
        uint32_t bA = tb + rowbA;
        uint32_t bB = tb + TILEB + rowbB;

        {
            uint32_t offA = (uint32_t)((a_seg0 ^ swA) * 16);
            uint32_t offB = (uint32_t)((b_seg0 ^ swB) * 16);
            uint32_t ah[4][4], bh[2][4];
#pragma unroll
            for (int mt = 0; mt < 4; mt++)
                ldm_x4(ah[mt], bA + mt * 1024 + offA);
#pragma unroll
            for (int nt2 = 0; nt2 < 2; nt2++)
                ldm_x4(bh[nt2], bB + nt2 * 1024 + offB);
#pragma unroll
            for (int mt = 0; mt < 4; mt++)
#pragma unroll
                for (int nt = 0; nt < 4; nt++)
                    mma16816(acc[mt][nt], ah[mt], &bh[nt >> 1][(nt & 1) * 2]);
        }
        if (c + 3 < NCHUNK) load_chunk(c + 3, (c + 3) & 3);
        {
            uint32_t offA = (uint32_t)(((a_seg0 + 2) ^ swA) * 16);
            uint32_t offB = (uint32_t)(((b_seg0 + 2) ^ swB) * 16);
            uint32_t ah[4][4], bh[2][4];
#pragma unroll
            for (int mt = 0; mt < 4; mt++)
                ldm_x4(ah[mt], bA + mt * 1024 + offA);
#pragma unroll
            for (int nt2 = 0; nt2 < 2; nt2++)
                ldm_x4(bh[nt2], bB + nt2 * 1024 + offB);
#pragma unroll
            for (int mt = 0; mt < 4; mt++)
#pragma unroll
                for (int nt = 0; nt < 4; nt++)
                    mma16816(acc[mt][nt], ah[mt], &bh[nt >> 1][(nt & 1) * 2]);
        }
    }

#pragma unroll
    for (int mt = 0; mt < 4; mt++) {
        int m = m0 + wm + mt * 16 + lr;
#pragma unroll
        for (int nt = 0; nt < 4; nt++) {
            int col = n0 + wn + nt * 8 + lc * 2;
            float bx = bias[col], by = bias[col + 1];
            if (HOut) {
                if (m < M)
                    *(uint32_t*)(HOut + (size_t)m * DIMC + col) =
                        h2pack(acc[mt][nt][0] + bx, acc[mt][nt][1] + by);
                if (m + 8 < M)
                    *(uint32_t*)(HOut + (size_t)(m + 8) * DIMC + col) =
                        h2pack(acc[mt][nt][2] + bx, acc[mt][nt][3] + by);
            } else {
                if (m < M) {
                    float2 v = make_float2(acc[mt][nt][0] + bx, acc[mt][nt][1] + by);
                    *(float2*)(C + (size_t)m * DIMC + col) = v;
                }
                if (m + 8 < M) {
                    float2 v = make_float2(acc[mt][nt][2] + bx, acc[mt][nt][3] + by);
                    *(float2*)(C + (size_t)(m + 8) * DIMC + col) = v;
                }
            }
        }
    }
}

__global__ __launch_bounds__(256, 2) void gemm_qkv(
    const float* __restrict__ bq, const float* __restrict__ bk, const float* __restrict__ bv)
{
    extern __shared__ __align__(16) char smem[];
    uint32_t sb = smem_u32(smem);
    int z = blockIdx.z;
    if (z == 2) {
        gemm_core(Xh, Wh4[2], bv, (float*)0, Vh, NTOK,
                  blockIdx.y * 128, blockIdx.x * 128, sb);
    } else {
        const float* bias = (z == 0) ? bq : bk;
        float* C = (z == 0) ? Qbuf : Kbuf;
        gemm_core(Xh, Wh4[z], bias, C, (__half*)0, NTOK,
                  blockIdx.y * 128, blockIdx.x * 128, sb);
    }
}

__global__ __launch_bounds__(256, 2) void gemm_out(const float* __restrict__ bo, float* __restrict__ out)
{
    extern __shared__ __align__(16) char smem[];
    uint32_t sb = smem_u32(smem);
    gemm_core(AOh, Wh4[3], bo, out, (__half*)0, NTOK,
              blockIdx.y * 128, blockIdx.x * 128, sb);
}

// ---------------- fused rmsnorm + relu + eps + RoPE (fp16 outputs, no lo) ----------------
__global__ void rmsnorm_rope_kernel(const float* __restrict__ nqw, const float* __restrict__ nkw,
                                    const float* __restrict__ fc, const float* __restrict__ fs) {
    int n = blockIdx.x;
    bool isK = blockIdx.y;
    const float* buf = isK ? Kbuf : Qbuf;
    __half* ph = isK ? Kph : Qph;
    __half* rh = isK ? KRh : QRh;
    const float* w = isK ? nkw : nqw;
    int tid = threadIdx.x;
    size_t base = (size_t)n * DIMC;
    const float2* b2 = (const float2*)(buf + base);
    const float2* w2 = (const float2*)w;

    int f = n / 1500, rem = n % 1500;
    int hh = rem / 50, ww = rem % 50;

    float2 v[3];
    float ss = 0.f;
#pragma unroll
    for (int t = 0; t < 3; t++) {
        v[t] = b2[tid + t * 256];
        ss += v[t].x * v[t].x + v[t].y * v[t].y;
    }
    for (int o = 16; o > 0; o >>= 1) ss += __shfl_xor_sync(0xffffffffu, ss, o);
    __shared__ float red[8];
    __shared__ float stot;
    if ((tid & 31) == 0) red[tid >> 5] = ss;
    __syncthreads();
    if (tid == 0) {
        float t = 0.f;
        for (int i = 0; i < 8; i++) t += red[i];
        stot = t;
    }
    __syncthreads();
    float sc = 1.0f / sqrtf(stot * (1.0f / DIMC) + EPSF);
#pragma unroll
    for (int t = 0; t < 3; t++) {
        int idx = tid + t * 256;
        float2 wv = w2[idx];
        float x0 = fmaxf(v[t].x * sc * wv.x, 0.f) + EPSF;
        float x1 = fmaxf(v[t].y * sc * wv.y, 0.f) + EPSF;
        *(uint32_t*)(ph + base + 2 * idx) = h2pack(x0, x1);
        int c = idx & 63;
        int pos = (c < 22) ? f : ((c < 43) ? hh : ww);
        float cs = fc[pos * 64 + c];
        float sn = fs[pos * 64 + c];
        float r0 = x0 * cs - x1 * sn;
        float r1 = x0 * sn + x1 * cs;
        *(uint32_t*)(rh + base + 2 * idx) = h2pack(r0, r1);
    }
}

// ---------------- fused ksum + qk (fp16 in, fp32 accum) ----------------
__global__ void qk_kernel() {
    int b = blockIdx.x;
    int hh = b / NBLK, nb = b % NBLK;
    int tid = threadIdx.x;
    __shared__ float ks[HDIM];
    float acc = 0.f;
    for (int p = 0; p < PBLK; p++) {
        int t = tok_of(nb, p);
        acc += __half2float(Kph[(size_t)t * DIMC + hh * HDIM + tid]);
    }
    ks[tid] = acc;
    __syncthreads();
    if (tid < PBLK) {
        int t = tok_of(nb, tid);
        const __half* qp = Qph + (size_t)t * DIMC + hh * HDIM;
        float a = 0.f;
#pragma unroll 4
        for (int d = 0; d < HDIM; d++) a += __half2float(qp[d]) * ks[d];
        QKbuf[b * PBLK + tid] = a;
    }
}

// ---------------- kv: tc fp16 1-pass KRh*Vh; 2 tiles -> 2 CTAs/SM ----------------
#define T2ST  136                       // halves per smem row (272 B, 4-bank rotation)
#define T2B   (128 * T2ST * 2)          // 34816 B per tile
#define KV2_SMEM (2 * T2B)              // 69632

__global__ __launch_bounds__(256, 2) void kv_kernel() {
    extern __shared__ __align__(16) char smem[];
    uint32_t sb = smem_u32(smem);
    int b = blockIdx.x;
    int hh = b / NBLK, nb = b % NBLK;
    int tid = threadIdx.x;

    // zero p-pad rows 120..127 in both tiles
    for (int i = tid; i < 2 * 8 * 16; i += 256) {
        int t = i >> 7, r = (i >> 4) & 7, s = i & 15;
        *(uint4*)(smem + t * T2B + (120 + r) * (T2ST * 2) + s * 16) = make_uint4(0, 0, 0, 0);
    }
    // group A: rows 0..63 of both tiles (2048 segs -> 8/thread)
#pragma unroll
    for (int i = 0; i < 8; i++) {
        int idx = tid + i * 256;
        int t = idx >> 10;
        int rem = idx & 1023;
        int row = rem >> 4, seg = rem & 15;
        int tok = tok_of(nb, row);
        const __half* g = (t == 0) ? KRh : Vh;
        g += (size_t)tok * DIMC + hh * HDIM + seg * 8;
        cp_async16(sb + t * T2B + row * (T2ST * 2) + seg * 16, g);
    }
    asm volatile("cp.async.commit_group;" ::: "memory");
    // group B: rows 64..119 (2*896 = 1792 segs -> 7/thread)
#pragma unroll
    for (int i = 0; i < 7; i++) {
        int idx = tid + i * 256;
        int t = idx / 896;
        int rem = idx - t * 896;
        int row = 64 + (rem >> 4), seg = rem & 15;
        int tok = tok_of(nb, row);
        const __half* g = (t == 0) ? KRh : Vh;
        g += (size_t)tok * DIMC + hh * HDIM + seg * 8;
        cp_async16(sb + t * T2B + row * (T2ST * 2) + seg * 16, g);
    }
    asm volatile("cp.async.commit_group;" ::: "memory");

    int wid = tid >> 5, lane = tid & 31;
    int q = lane >> 3, rr = lane & 7;
    int wm = (wid & 3) * 32, wn = (wid >> 2) * 64;   // d, e
    uint32_t bKRh = sb, bVh = sb + T2B;

    float acc[2][8][4];
#pragma unroll
    for (int i = 0; i < 2; i++)
#pragma unroll
        for (int j = 0; j < 8; j++)
#pragma unroll
            for (int r = 0; r < 4; r++) acc[i][j][r] = 0.f;

    asm volatile("cp.async.wait_group 1;" ::: "memory");
    __syncthreads();

#pragma unroll
    for (int ks = 0; ks < 8; ks++) {
        if (ks == 4) {
            asm volatile("cp.async.wait_group 0;" ::: "memory");
            __syncthreads();
        }
        int p0 = ks * 16;
        uint32_t ah[2][4], bh[4][4];
#pragma unroll
        for (int mt = 0; mt < 2; mt++) {
            int d0 = wm + mt * 16;
            uint32_t ad = (uint32_t)((p0 + (q >> 1) * 8 + rr) * T2ST + d0 + (q & 1) * 8) * 2;
            ldm_x4_t(ah[mt], bKRh + ad);
        }
#pragma unroll
        for (int nt2 = 0; nt2 < 4; nt2++) {
            int e0 = wn + nt2 * 16;
            uint32_t bd = (uint32_t)((p0 + (q & 1) * 8 + rr) * T2ST + e0 + (q >> 1) * 8) * 2;
            ldm_x4_t(bh[nt2], bVh + bd);
        }
#pragma unroll
        for (int mt = 0; mt < 2; mt++)
#pragma unroll
            for (int nt = 0; nt < 8; nt++)
                mma16816(acc[mt][nt], ah[mt], &bh[nt >> 1][(nt & 1) * 2]);
    }

    int lr = lane >> 2, lc = lane & 3;
    size_t db = (size_t)b * HDIM * HDIM;
#pragma unroll
    for (int mt = 0; mt < 2; mt++) {
        int d = wm + mt * 16 + lr;
#pragma unroll
        for (int nt = 0; nt < 8; nt++) {
            int e = wn + nt * 8 + lc * 2;
            {
                float v0 = acc[mt][nt][0], v1 = acc[mt][nt][1];
                uint32_t hp = h2pack(v0, v1);
                *(uint32_t*)(KVah + db + d * HDIM + e) = hp;
                *(uint32_t*)(KVal + db + d * HDIM + e) = h2packlo(v0, v1, hp);
            }
            {
                float v0 = acc[mt][nt][2], v1 = acc[mt][nt][3];
                uint32_t hp = h2pack(v0, v1);
                *(uint32_t*)(KVah + db + (d + 8) * HDIM + e) = hp;
                *(uint32_t*)(KVal + db + (d + 8) * HDIM + e) = h2packlo(v0, v1, hp);
            }
        }
    }
}

// ---------------- mix on tensor cores (3-pass, writes KVMh only) ----------------
#define MXST  168
#define MWB   (160 * MXST * 2)
#define MKST  136
#define MKB   (160 * MKST * 2)
#define MIX2_SMEM (2 * MWB + 2 * MKB)

__global__ __launch_bounds__(256) void mix_tc_kernel() {
    extern __shared__ __align__(16) char smem[];
    uint32_t sb = smem_u32(smem);
    int hh = blockIdx.y, xt = blockIdx.x;
    int tid = threadIdx.x;

    uint32_t bWh = sb, bWl = sb + MWB, bKh = sb + 2 * MWB, bKl = sb + 2 * MWB + MKB;

    for (int i = tid; i < 340; i += 256) {
        int t = i / 170, rem = i % 170;
        int r = rem / 17, s = rem % 17;
        *(uint4*)(smem + 2 * MWB + t * MKB + (150 + r) * (MKST * 2) + s * 16) = make_uint4(0, 0, 0, 0);
    }
#pragma unroll
    for (int i = 0; i < 25; i++) {
        int idx = tid + i * 256;
        int t = idx / 3200, rem = idx % 3200;
        int row = rem / 20, seg = rem % 20;
        const __half* g = ((t == 0) ? WBh : WBl) + row * 160 + seg * 8;
        cp_async16(sb + t * MWB + row * (MXST * 2) + seg * 16, g);
    }
#pragma unroll
    for (int i = 0; i < 19; i++) {
        int idx = tid + i * 256;
        if (idx < 4800) {
            int t = idx / 2400, rem = idx % 2400;
            int row = rem >> 4, seg = rem & 15;
            const __half* g = ((t == 0) ? KVah : KVal)
                            + ((size_t)(hh * NBLK + row)) * (HDIM * HDIM) + xt * 128 + seg * 8;
            cp_async16(sb + 2 * MWB + t * MKB + row * (MKST * 2) + seg * 16, g);
        }
    }
    asm volatile("cp.async.commit_group;" ::: "memory");
    asm volatile("cp.async.wait_group 0;" ::: "memory");
    __syncthreads();

    int wid = tid >> 5, lane = tid & 31;
    int q = lane >> 3, rr = lane & 7;
    int wm = (wid & 1) * 80;
    int wn = (wid >> 1) * 32;

    float acc[5][4][4];
#pragma unroll
    for (int i = 0; i < 5; i++)
#pragma unroll
        for (int j = 0; j < 4; j++)
#pragma unroll
            for (int r = 0; r < 4; r++) acc[i][j][r] = 0.f;

#pragma unroll
    for (int ks = 0; ks < 10; ks++) {
        int k0 = ks * 16;
        uint32_t ah[5][4], al[5][4], bh[2][4], bl[2][4];
#pragma unroll
        for (int mt = 0; mt < 5; mt++) {
            int m0 = wm + mt * 16;
            uint32_t ad = (uint32_t)((m0 + (q & 1) * 8 + rr) * MXST + k0 + (q >> 1) * 8) * 2;
            ldm_x4(ah[mt], bWh + ad);
            ldm_x4(al[mt], bWl + ad);
        }
#pragma unroll
        for (int nt2 = 0; nt2 < 2; nt2++) {
            int e0 = wn + nt2 * 16;
            uint32_t bd = (uint32_t)((k0 + (q & 1) * 8 + rr) * MKST + e0 + (q >> 1) * 8) * 2;
            ldm_x4_t(bh[nt2], bKh + bd);
            ldm_x4_t(bl[nt2], bKl + bd);
        }
#pragma unroll
        for (int mt = 0; mt < 5; mt++)
#pragma unroll
            for (int nt = 0; nt < 4; nt++) {
                const uint32_t* pbh = &bh[nt >> 1][(nt & 1) * 2];
                const uint32_t* pbl = &bl[nt >> 1][(nt & 1) * 2];
                mma16816(acc[mt][nt], ah[mt], pbh);
                mma16816(acc[mt][nt], ah[mt], pbl);
                mma16816(acc[mt][nt], al[mt], pbh);
            }
    }

    int lr = lane >> 2, lc = lane & 3;
#pragma unroll
    for (int mt = 0; mt < 5; mt++) {
        int o = wm + mt * 16 + lr;
#pragma unroll
        for (int half = 0; half < 2; half++) {
            int oo = o + half * 8;
            if (oo < NBLK) {
                size_t gb = ((size_t)(hh * NBLK + oo)) * (HDIM * HDIM) + xt * 128 + wn;
#pragma unroll
                for (int nt = 0; nt < 4; nt++) {
                    int e = nt * 8 + lc * 2;
                    *(uint32_t*)(KVMh + gb + e) =
                        h2pack(acc[mt][nt][2 * half], acc[mt][nt][2 * half + 1]);
                }
            }
        }
    }
}

// ---------------- out: tc fp16 1-pass QRh*KVMh + fused norm; 2 tiles -> 2 CTAs/SM ----------------
#define OUT2_SMEM (2 * T2B + 512)

__global__ __launch_bounds__(256, 2) void out_kernel() {
    extern __shared__ __align__(16) char smem[];
    uint32_t sb = smem_u32(smem);
    float* sNorm = (float*)(smem + 2 * T2B);
    int b = blockIdx.x;
    int hh = b / NBLK, nb = b % NBLK;
    int tid = threadIdx.x;

    // zero QR pad rows 120..127
    for (int i = tid; i < 128; i += 256) {
        int r = (i >> 4) & 7, s = i & 15;
        *(uint4*)(smem + (120 + r) * (T2ST * 2) + s * 16) = make_uint4(0, 0, 0, 0);
    }
    // group A: QRh (1920) + KVMh rows 0..63 (1024) = 2944 -> 12/thread w/ guard
#pragma unroll
    for (int i = 0; i < 12; i++) {
        int idx = tid + i * 256;
        if (idx < 1920) {
            int row = idx >> 4, seg = idx & 15;
            int tok = tok_of(nb, row);
            const __half* g = QRh + (size_t)tok * DIMC + hh * HDIM + seg * 8;
            cp_async16(sb + row * (T2ST * 2) + seg * 16, g);
        } else if (idx < 2944) {
            int idx2 = idx - 1920;
            int row = idx2 >> 4, seg = idx2 & 15;
            const __half* g = KVMh + (size_t)b * HDIM * HDIM + row * HDIM + seg * 8;
            cp_async16(sb + T2B + row * (T2ST * 2) + seg * 16, g);
        }
    }
    asm volatile("cp.async.commit_group;" ::: "memory");
    // group B: KVMh rows 64..127 (1024 segs -> 4/thread)
#pragma unroll
    for (int i = 0; i < 4; i++) {
        int idx = tid + i * 256;
        int row = 64 + (idx >> 4), seg = idx & 15;
        const __half* g = KVMh + (size_t)b * HDIM * HDIM + row * HDIM + seg * 8;
        cp_async16(sb + T2B + row * (T2ST * 2) + seg * 16, g);
    }
    asm volatile("cp.async.commit_group;" ::: "memory");

    // fused norm: overlap with in-flight cp.async loads
    if (tid < PBLK) {
        float a = EPSF;
        const float* wrow = WBLKbuf + nb * NBLK;
        const float* qkcol = QKbuf + (size_t)hh * NBLK * PBLK + tid;
        for (int i = 0; i < NBLK; i++)
            a += wrow[i] * qkcol[(size_t)i * PBLK];
        sNorm[tid] = a;
    }

    int wid = tid >> 5, lane = tid & 31;
    int q = lane >> 3, rr = lane & 7;
    int wm = (wid & 1) * 64, wn = (wid >> 1) * 32;   // p, e
    uint32_t bQh = sb, bMh = sb + T2B;

    float acc[4][4][4];
#pragma unroll
    for (int i = 0; i < 4; i++)
#pragma unroll
        for (int j = 0; j < 4; j++)
#pragma unroll
            for (int r = 0; r < 4; r++) acc[i][j][r] = 0.f;

    asm volatile("cp.async.wait_group 1;" ::: "memory");
    __syncthreads();

#pragma unroll
    for (int ks = 0; ks < 8; ks++) {
        if (ks == 4) {
            asm volatile("cp.async.wait_group 0;" ::: "memory");
            __syncthreads();
        }
        int d0 = ks * 16;
        uint32_t ah[4][4], bh[2][4];
#pragma unroll
        for (int mt = 0; mt < 4; mt++) {
            int m0 = wm + mt * 16;
            uint32_t ad = (uint32_t)((m0 + (q & 1) * 8 + rr) * T2ST + d0 + (q >> 1) * 8) * 2;
            ldm_x4(ah[mt], bQh + ad);
        }
#pragma unroll
        for (int nt2 = 0; nt2 < 2; nt2++) {
            int e0 = wn + nt2 * 16;
            uint32_t bd = (uint32_t)((d0 + (q & 1) * 8 + rr) * T2ST + e0 + (q >> 1) * 8) * 2;
            ldm_x4_t(bh[nt2], bMh + bd);
        }
#pragma unroll
        for (int mt = 0; mt < 4; mt++)
#pragma unroll
            for (int nt = 0; nt < 4; nt++)
                mma16816(acc[mt][nt], ah[mt], &bh[nt >> 1][(nt & 1) * 2]);
    }

    int lr = lane >> 2, lc = lane & 3;
#pragma unroll
    for (int mt = 0; mt < 4; mt++) {
        int p = wm + mt * 16 + lr;
#pragma unroll
        for (int half = 0; half < 2; half++) {
            int pp = p + half * 8;
            if (pp < PBLK) {
                float inv = 1.0f / sNorm[pp];
                int tok = tok_of(nb, pp);
                size_t gb = (size_t)tok * DIMC + hh * HDIM;
#pragma unroll
                for (int nt = 0; nt < 4; nt++) {
                    int e = wn + nt * 8 + lc * 2;
                    float v0 = acc[mt][nt][2 * half]     * inv;
                    float v1 = acc[mt][nt][2 * half + 1] * inv;
                    *(uint32_t*)(AOh + gb + e) = h2pack(v0, v1);
                }
            }
        }
    }
}

// ---------------- launch ----------------
extern "C" void kernel_launch(void* const* d_in, const int* in_sizes, int n_in,
                              void* d_out, int out_size) {
    const float* x   = (const float*)d_in[0];
    const float* fc  = (const float*)d_in[3];
    const float* fs  = (const float*)d_in[4];
    const float* wq  = (const float*)d_in[5];
    const float* bq  = (const float*)d_in[6];
    const float* wk  = (const float*)d_in[7];
    const float* bk  = (const float*)d_in[8];
    const float* wv  = (const float*)d_in[9];
    const float* bv  = (const float*)d_in[10];
    const float* wo  = (const float*)d_in[11];
    const float* bo  = (const float*)d_in[12];
    const float* nqw = (const float*)d_in[13];
    const float* nkw = (const float*)d_in[14];
    float* out = (float*)d_out;

    void* pxh;
    cudaGetSymbolAddress(&pxh, Xh);

    cudaFuncSetAttribute(gemm_qkv,  cudaFuncAttributeMaxDynamicSharedMemorySize, GEMM_SMEM);
    cudaFuncSetAttribute(gemm_out,  cudaFuncAttributeMaxDynamicSharedMemorySize, GEMM_SMEM);
    cudaFuncSetAttribute(kv_kernel, cudaFuncAttributeMaxDynamicSharedMemorySize, KV2_SMEM);
    cudaFuncSetAttribute(mix_tc_kernel, cudaFuncAttributeMaxDynamicSharedMemorySize, MIX2_SMEM);
    cudaFuncSetAttribute(out_kernel, cudaFuncAttributeMaxDynamicSharedMemorySize, OUT2_SMEM);

    wblk_kernel<<<NBLK, 256>>>();
    conv_half<<<(MPAD * DIMC) / 256, 256>>>(x, (__half*)pxh, NTOK * DIMC, MPAD * DIMC);
    conv_w4<<<dim3((DIMC * DIMC) / 256, 4), 256>>>(wq, wk, wv, wo);

    dim3 gg(DIMC / 128, MPAD / 128, 3);
    gemm_qkv<<<gg, 256, GEMM_SMEM>>>(bq, bk, bv);

    rmsnorm_rope_kernel<<<dim3(NTOK, 2), 256>>>(nqw, nkw, fc, fs);

    qk_kernel<<<NHEAD * NBLK, HDIM>>>();
    kv_kernel<<<NHEAD * NBLK, 256, KV2_SMEM>>>();
    mix_tc_kernel<<<dim3(128, NHEAD), 256, MIX2_SMEM>>>();
    out_kernel<<<NHEAD * NBLK, 256, OUT2_SMEM>>>();

    dim3 go(DIMC / 128, MPAD / 128);
    gemm_out<<<go, 256, GEMM_SMEM>>>(bo, out);
}